// round 8
// baseline (speedup 1.0000x reference)
#include <cuda_runtime.h>
#include <math.h>
#include <stdint.h>

// Problem constants
#define BATCH   4
#define SEQ     2048
#define DMODEL  1024
#define DINNER  2048
#define DSTATE  16
#define DTRANK  64
#define DCONV   4
#define MROWS   (BATCH*SEQ)          // 8192
#define NXZ     (2*DINNER)           // 4096
#define NDBL    (DTRANK + 2*DSTATE)  // 96
#define NCHUNK  32
#define LCHUNK  (SEQ/NCHUNK)         // 64
#define XPJ_SPLITK 4
#define NBDN    (BATCH*DINNER*DSTATE)    // 131072

// ----------------------------------------------------------------------------
// Scratch (device globals; no runtime allocation allowed)
// ----------------------------------------------------------------------------
__device__ float g_xz [(size_t)MROWS * NXZ];
__device__ float g_xc [(size_t)MROWS * DINNER];
__device__ float g_dbl[(size_t)MROWS * NDBL];
__device__ float g_dblp[(size_t)XPJ_SPLITK * MROWS * NDBL];
__device__ float g_dt [(size_t)MROWS * DINNER];
__device__ float g_y  [(size_t)MROWS * DINNER];   // tf32-rounded, k-pair-permuted
__device__ float g_xr [(size_t)MROWS * DMODEL];   // tf32-rounded, permuted x
__device__ float g_wa [(size_t)NXZ   * DMODEL];   // tf32-rounded, permuted in_proj_w
__device__ float g_wb [(size_t)DMODEL* DINNER];   // tf32-rounded, permuted out_proj_w
// chunked-scan state, layout [chunk][b*d*n]
#define SCAN_ST ((size_t)NCHUNK * NBDN)
__device__ float g_P [SCAN_ST];
__device__ float g_Q [SCAN_ST];
__device__ float g_HS[SCAN_ST];

// ============================================================================
// mma.sync tf32 helpers
// ============================================================================
__device__ __forceinline__ uint32_t f2tf32(float x) {
    uint32_t r;
    asm("cvt.rna.tf32.f32 %0, %1;" : "=r"(r) : "f"(x));
    return r;
}
__device__ __forceinline__ void mma_tf32(float* c, const uint32_t* a, const uint32_t* b) {
    asm volatile(
        "mma.sync.aligned.m16n8k8.row.col.f32.tf32.tf32.f32 "
        "{%0,%1,%2,%3}, {%4,%5,%6,%7}, {%8,%9}, {%0,%1,%2,%3};"
        : "+f"(c[0]), "+f"(c[1]), "+f"(c[2]), "+f"(c[3])
        : "r"(a[0]), "r"(a[1]), "r"(a[2]), "r"(a[3]), "r"(b[0]), "r"(b[1]));
}
__device__ __forceinline__ uint32_t smem_u32(const void* p) {
    uint32_t a;
    asm("{ .reg .u64 t; cvta.to.shared.u64 t, %1; cvt.u32.u64 %0, t; }"
        : "=r"(a) : "l"(p));
    return a;
}
__device__ __forceinline__ void cp_async16(uint32_t dst, const void* src) {
    asm volatile("cp.async.ca.shared.global [%0], [%1], 16;"
                 :: "r"(dst), "l"(src) : "memory");
}
__device__ __forceinline__ void cp_async16z(uint32_t dst, const void* src, bool valid) {
    uint32_t sz = valid ? 16u : 0u;
    asm volatile("cp.async.ca.shared.global [%0], [%1], 16, %2;"
                 :: "r"(dst), "l"(src), "r"(sz) : "memory");
}
#define CP_COMMIT() asm volatile("cp.async.commit_group;" ::: "memory")
#define CP_WAIT(n)  asm volatile("cp.async.wait_group %0;" :: "n"(n) : "memory")

// ============================================================================
// tf32 MMA NT GEMM: C[M,N] = A[M,K] * B[N,K]^T, fp32 accumulate.
// CTA tile 128x128x32, 256 thr, warp tile 64x32, 2-stage cp.async buffer.
// PERM: operands stored k-pair-permuted ([k0,k4,k1,k5,k2,k6,k3,k7] per
//       8-group) -> fragment loads become LDS.64, stride 40 = conflict-free.
// ============================================================================
template<int EPI, bool NGUARD, bool CVTA, bool CVTB, bool SPLITK, bool PERM>
__global__ void __launch_bounds__(256, 2)
mma_gemm(const float* __restrict__ A, const float* __restrict__ B,
         float* __restrict__ C, const float* __restrict__ bias,
         int M, int N, int K, int lda, int ldb, int ldc)
{
    constexpr int STRIDE  = PERM ? 40 : 36;
    constexpr int STAGE_F = 128 * STRIDE;
    constexpr int STAGE_B = STAGE_F * 4;

    extern __shared__ float sm[];
    const uint32_t smB = smem_u32(sm);

    if (SPLITK) {
        const int z = blockIdx.z;
        A += (size_t)z * K;
        B += (size_t)z * K;
        C += (size_t)z * M * (size_t)ldc;
    }

    const int tid    = threadIdx.x;
    const int lane   = tid & 31;
    const int wid    = tid >> 5;
    const int warp_m = wid >> 2;
    const int warp_n = wid & 3;
    const int lr     = lane >> 2;
    const int lc     = lane & 3;

    const int rowBase = blockIdx.y * 128;
    const int colBase = blockIdx.x * 128;

    float acc[4][4][4];
#pragma unroll
    for (int mt = 0; mt < 4; ++mt)
#pragma unroll
        for (int nt = 0; nt < 4; ++nt)
#pragma unroll
            for (int i = 0; i < 4; ++i) acc[mt][nt][i] = 0.f;

    const int T = K >> 5;

    auto load_stage = [&](int s, int kt) {
        const int kOff = kt << 5;
        const uint32_t aB = smB + s * STAGE_B;
        const uint32_t bB = smB + 2 * STAGE_B + s * STAGE_B;
#pragma unroll
        for (int i = 0; i < 4; ++i) {
            const int chunk = tid + (i << 8);
            const int row = chunk >> 3;
            const int c4  = chunk & 7;
            const uint32_t so = row * (STRIDE * 4) + c4 * 16;
            cp_async16(aB + so, &A[(size_t)(rowBase + row) * lda + kOff + c4 * 4]);
            if (NGUARD) {
                const bool ok = (colBase + row) < N;
                const int  br = ok ? (colBase + row) : 0;
                cp_async16z(bB + so, &B[(size_t)br * ldb + kOff + c4 * 4], ok);
            } else {
                cp_async16(bB + so, &B[(size_t)(colBase + row) * ldb + kOff + c4 * 4]);
            }
        }
        CP_COMMIT();
    };

    auto fragA = [&](const float* p) -> uint32_t {
        return CVTA ? f2tf32(*p) : __float_as_uint(*p);
    };
    auto fragB = [&](const float* p) -> uint32_t {
        return CVTB ? f2tf32(*p) : __float_as_uint(*p);
    };

    load_stage(0, 0);

    for (int kt = 0; kt < T; ++kt) {
        const int s = kt & 1;
        if (kt + 1 < T) {
            load_stage(s ^ 1, kt + 1);
            CP_WAIT(1);
        } else {
            CP_WAIT(0);
        }
        __syncthreads();

        const float* As_ = sm + s * STAGE_F;
        const float* Bs_ = sm + 2 * STAGE_F + s * STAGE_F;

#pragma unroll
        for (int kk = 0; kk < 4; ++kk) {
            uint32_t af[4][4];
            uint32_t bf[4][2];
            if (PERM) {
                const int k0 = (kk << 3) + 2 * lc;
#pragma unroll
                for (int mt = 0; mt < 4; ++mt) {
                    const float* p = As_ + (warp_m * 64 + mt * 16 + lr) * STRIDE + k0;
                    const uint2 u0 = *reinterpret_cast<const uint2*>(p);
                    const uint2 u1 = *reinterpret_cast<const uint2*>(p + 8 * STRIDE);
                    af[mt][0] = u0.x; af[mt][1] = u1.x;
                    af[mt][2] = u0.y; af[mt][3] = u1.y;
                }
#pragma unroll
                for (int nt = 0; nt < 4; ++nt) {
                    const float* p = Bs_ + (warp_n * 32 + nt * 8 + lr) * STRIDE + k0;
                    const uint2 u = *reinterpret_cast<const uint2*>(p);
                    bf[nt][0] = u.x; bf[nt][1] = u.y;
                }
            } else {
                const int k0 = (kk << 3) + lc;
#pragma unroll
                for (int mt = 0; mt < 4; ++mt) {
                    const float* p = As_ + (warp_m * 64 + mt * 16 + lr) * STRIDE + k0;
                    af[mt][0] = fragA(p);
                    af[mt][1] = fragA(p + 8 * STRIDE);
                    af[mt][2] = fragA(p + 4);
                    af[mt][3] = fragA(p + 8 * STRIDE + 4);
                }
#pragma unroll
                for (int nt = 0; nt < 4; ++nt) {
                    const float* p = Bs_ + (warp_n * 32 + nt * 8 + lr) * STRIDE + k0;
                    bf[nt][0] = fragB(p);
                    bf[nt][1] = fragB(p + 4);
                }
            }
#pragma unroll
            for (int mt = 0; mt < 4; ++mt)
#pragma unroll
                for (int nt = 0; nt < 4; ++nt)
                    mma_tf32(acc[mt][nt], af[mt], bf[nt]);
        }
        __syncthreads();
    }

#pragma unroll
    for (int mt = 0; mt < 4; ++mt) {
        const int row = rowBase + warp_m * 64 + mt * 16 + lr;
#pragma unroll
        for (int nt = 0; nt < 4; ++nt) {
            const int col = colBase + warp_n * 32 + nt * 8 + 2 * lc;
            if (NGUARD && col >= N) continue;
            float v[4] = {acc[mt][nt][0], acc[mt][nt][1],
                          acc[mt][nt][2], acc[mt][nt][3]};
            if (EPI == 1) {
                const float b0 = bias[col], b1 = bias[col + 1];
                v[0] += b0; v[1] += b1; v[2] += b0; v[3] += b1;
#pragma unroll
                for (int i = 0; i < 4; ++i)
                    v[i] = fmaxf(v[i], 0.f) + log1pf(__expf(-fabsf(v[i])));
            }
            *reinterpret_cast<float2*>(&C[(size_t)row * ldc + col]) =
                make_float2(v[0], v[1]);
            *reinterpret_cast<float2*>(&C[(size_t)(row + 8) * ldc + col]) =
                make_float2(v[2], v[3]);
        }
    }
}

#define MMA_SMEM_PERM  (4 * 128 * 40 * 4)   // 81920
#define MMA_SMEM_STD   (4 * 128 * 36 * 4)   // 73728

// ----------------------------------------------------------------------------
// split-K reduce
// ----------------------------------------------------------------------------
__global__ void reduce_splitk_kernel(const float4* __restrict__ part,
                                     float4* __restrict__ out, int n4, int stride4)
{
    int i = blockIdx.x * blockDim.x + threadIdx.x;
    if (i < n4) {
        float4 a = part[i];
        float4 b = part[i + stride4];
        float4 c = part[i + 2 * stride4];
        float4 d = part[i + 3 * stride4];
        out[i] = make_float4(a.x + b.x + c.x + d.x, a.y + b.y + c.y + d.y,
                             a.z + b.z + c.z + d.z, a.w + b.w + c.w + d.w);
    }
}

// ----------------------------------------------------------------------------
// Round fp32 to tf32 (rna) AND permute each 8-group to [k0,k4,k1,k5,k2,k6,k3,k7]
// ----------------------------------------------------------------------------
__device__ __forceinline__ float rtf(float x) {
    return __uint_as_float(f2tf32(x));
}
__global__ void round_perm_kernel(const float4* __restrict__ in,
                                  float4* __restrict__ out, int n8)
{
    int g = blockIdx.x * blockDim.x + threadIdx.x;
    if (g < n8) {
        float4 v0 = in[2*g];
        float4 v1 = in[2*g + 1];
        out[2*g]     = make_float4(rtf(v0.x), rtf(v1.x), rtf(v0.y), rtf(v1.y));
        out[2*g + 1] = make_float4(rtf(v0.z), rtf(v1.z), rtf(v0.w), rtf(v1.w));
    }
}

// ----------------------------------------------------------------------------
// Depthwise causal conv (width 4) + SiLU — float4 over channels
// ----------------------------------------------------------------------------
__global__ void conv_silu_kernel(const float* __restrict__ xz,
                                 const float* __restrict__ w,
                                 const float* __restrict__ b,
                                 float* __restrict__ xc)
{
    int i = blockIdx.x * blockDim.x + threadIdx.x;
    int d4 = (i & 511) << 2;
    int m  = i >> 9;
    int l  = m & (SEQ - 1);

    float4 wv[4];
#pragma unroll
    for (int c = 0; c < 4; ++c)
        wv[c] = *reinterpret_cast<const float4*>(&w[(d4 + c) * DCONV]);
    float4 acc = *reinterpret_cast<const float4*>(&b[d4]);

#pragma unroll
    for (int j = 0; j < DCONV; ++j) {
        int lj = l - (DCONV - 1) + j;
        if (lj >= 0) {
            float4 xv = *reinterpret_cast<const float4*>(
                &xz[(size_t)(m - (DCONV - 1) + j) * NXZ + d4]);
            acc.x = fmaf(((const float*)&wv[0])[j], xv.x, acc.x);
            acc.y = fmaf(((const float*)&wv[1])[j], xv.y, acc.y);
            acc.z = fmaf(((const float*)&wv[2])[j], xv.z, acc.z);
            acc.w = fmaf(((const float*)&wv[3])[j], xv.w, acc.w);
        }
    }
    acc.x = acc.x / (1.f + __expf(-acc.x));
    acc.y = acc.y / (1.f + __expf(-acc.y));
    acc.z = acc.z / (1.f + __expf(-acc.z));
    acc.w = acc.w / (1.f + __expf(-acc.w));
    *reinterpret_cast<float4*>(&xc[(size_t)m * DINNER + d4]) = acc;
}

// ============================================================================
// Chunked selective scan, smem-staged (as round 7).
// ============================================================================
__global__ void __launch_bounds__(256) scan_chunk_kernel(
    const float* __restrict__ dt,  const float* __restrict__ dbl,
    const float* __restrict__ xc,  const float* __restrict__ A_log,
    float* __restrict__ P, float* __restrict__ Q)
{
    __shared__ float s_dt[LCHUNK * 16];
    __shared__ float s_xc[LCHUNK * 16];
    __shared__ float s_B [LCHUNK * 16];

    const int tid  = threadIdx.x;
    const int d0   = blockIdx.x * 16;
    const int b    = blockIdx.y;
    const int c    = blockIdx.z;
    const int m0   = b * SEQ + c * LCHUNK;

    {
        const int trow = tid >> 2;
        const int tc4  = (tid & 3) << 2;
        const size_t gm = (size_t)(m0 + trow);
        *reinterpret_cast<float4*>(&s_dt[trow * 16 + tc4]) =
            *reinterpret_cast<const float4*>(&dt[gm * DINNER + d0 + tc4]);
        *reinterpret_cast<float4*>(&s_xc[trow * 16 + tc4]) =
            *reinterpret_cast<const float4*>(&xc[gm * DINNER + d0 + tc4]);
        *reinterpret_cast<float4*>(&s_B[trow * 16 + tc4]) =
            *reinterpret_cast<const float4*>(&dbl[gm * NDBL + DTRANK + tc4]);
    }
    __syncthreads();

    const int lane = tid & 31;
    const int warp = tid >> 5;
    const int n    = lane & 15;
    const int dloc = warp * 2 + (lane >> 4);
    const int d    = d0 + dloc;

    const float Ad = -__expf(A_log[d * DSTATE + n]);
    float Pp = 1.f, h = 0.f;

#pragma unroll 4
    for (int l = 0; l < LCHUNK; ++l) {
        const float dtv = s_dt[l * 16 + dloc];
        const float xv  = s_xc[l * 16 + dloc];
        const float Bv  = s_B [l * 16 + n];
        const float dA  = __expf(dtv * Ad);
        Pp *= dA;
        h = fmaf(dA, h, dtv * Bv * xv);
    }
    const size_t idx = (size_t)c * NBDN + ((size_t)b * DINNER + d) * DSTATE + n;
    P[idx] = Pp;
    Q[idx] = h;
}

__global__ void __launch_bounds__(256) scan_fix_kernel(
    const float* __restrict__ P, const float* __restrict__ Q,
    float* __restrict__ HS)
{
    const size_t i = (size_t)blockIdx.x * blockDim.x + threadIdx.x;
    float h = 0.f;
#pragma unroll
    for (int c = 0; c < NCHUNK; ++c) {
        const size_t k = (size_t)c * NBDN + i;
        HS[k] = h;
        h = fmaf(P[k], h, Q[k]);
    }
}

// Pass C: emits y tf32-rounded AND k-pair-permuted (consumed by PERM out_proj).
__global__ void __launch_bounds__(256) scan_y_kernel(
    const float* __restrict__ dt,  const float* __restrict__ dbl,
    const float* __restrict__ xc,  const float* __restrict__ xz,
    const float* __restrict__ A_log, const float* __restrict__ Dp,
    const float* __restrict__ HS, float* __restrict__ y)
{
    __shared__ float s_dt[LCHUNK * 16];
    __shared__ float s_xc[LCHUNK * 16];
    __shared__ float s_B [LCHUNK * 16];
    __shared__ float s_C [LCHUNK * 16];
    __shared__ float s_z [LCHUNK * 16];
    __shared__ float s_y [LCHUNK * 16];

    const int tid  = threadIdx.x;
    const int d0   = blockIdx.x * 16;
    const int b    = blockIdx.y;
    const int c    = blockIdx.z;
    const int m0   = b * SEQ + c * LCHUNK;

    {
        const int trow = tid >> 2;
        const int tc4  = (tid & 3) << 2;
        const size_t gm = (size_t)(m0 + trow);
        *reinterpret_cast<float4*>(&s_dt[trow * 16 + tc4]) =
            *reinterpret_cast<const float4*>(&dt[gm * DINNER + d0 + tc4]);
        *reinterpret_cast<float4*>(&s_xc[trow * 16 + tc4]) =
            *reinterpret_cast<const float4*>(&xc[gm * DINNER + d0 + tc4]);
        *reinterpret_cast<float4*>(&s_B[trow * 16 + tc4]) =
            *reinterpret_cast<const float4*>(&dbl[gm * NDBL + DTRANK + tc4]);
        *reinterpret_cast<float4*>(&s_C[trow * 16 + tc4]) =
            *reinterpret_cast<const float4*>(&dbl[gm * NDBL + DTRANK + DSTATE + tc4]);
        *reinterpret_cast<float4*>(&s_z[trow * 16 + tc4]) =
            *reinterpret_cast<const float4*>(&xz[gm * NXZ + DINNER + d0 + tc4]);
    }
    __syncthreads();

    const int lane = tid & 31;
    const int warp = tid >> 5;
    const int n    = lane & 15;
    const int dloc = warp * 2 + (lane >> 4);
    const int d    = d0 + dloc;

    const float Ad = -__expf(A_log[d * DSTATE + n]);
    const float Dd = Dp[d];
    float h = HS[(size_t)c * NBDN + ((size_t)b * DINNER + d) * DSTATE + n];

#pragma unroll 2
    for (int l = 0; l < LCHUNK; ++l) {
        const float dtv = s_dt[l * 16 + dloc];
        const float xv  = s_xc[l * 16 + dloc];
        const float Bv  = s_B [l * 16 + n];
        const float Cv  = s_C [l * 16 + n];
        const float dA  = __expf(dtv * Ad);
        h = fmaf(dA, h, dtv * Bv * xv);

        float p = h * Cv;
        p += __shfl_xor_sync(0xffffffffu, p, 8);
        p += __shfl_xor_sync(0xffffffffu, p, 4);
        p += __shfl_xor_sync(0xffffffffu, p, 2);
        p += __shfl_xor_sync(0xffffffffu, p, 1);

        if (n == 0) {
            const float zv = s_z[l * 16 + dloc];
            s_y[l * 16 + dloc] = (p + Dd * xv) * (zv / (1.f + __expf(-zv)));
        }
    }
    __syncthreads();

    // coalesced, tf32-rounded, k-pair-permuted store
    {
        const int trow = tid >> 2;
        const int tc4  = (tid & 3) << 2;     // 0,4,8,12
        const int grp  = tc4 & 8;            // 0 or 8
        const float* s = &s_y[trow * 16 + grp];
        float4 v;
        if ((tc4 & 4) == 0)
            v = make_float4(rtf(s[0]), rtf(s[4]), rtf(s[1]), rtf(s[5]));
        else
            v = make_float4(rtf(s[2]), rtf(s[6]), rtf(s[3]), rtf(s[7]));
        *reinterpret_cast<float4*>(&y[(size_t)(m0 + trow) * DINNER + d0 + tc4]) = v;
    }
}

// ----------------------------------------------------------------------------
// Launch
// ----------------------------------------------------------------------------
extern "C" void kernel_launch(void* const* d_in, const int* in_sizes, int n_in,
                              void* d_out, int out_size)
{
    const float* x          = (const float*)d_in[0];
    const float* in_proj_w  = (const float*)d_in[1];
    const float* conv_w     = (const float*)d_in[2];
    const float* conv_b     = (const float*)d_in[3];
    const float* x_proj_w   = (const float*)d_in[4];
    const float* dt_proj_w  = (const float*)d_in[5];
    const float* dt_proj_b  = (const float*)d_in[6];
    const float* A_log      = (const float*)d_in[7];
    const float* D_param    = (const float*)d_in[8];
    const float* out_proj_w = (const float*)d_in[9];
    float* out = (float*)d_out;

    float *xz, *xc, *dbl, *dblp, *dtb, *yb, *xr, *wa, *wb, *P, *Q, *HS;
    cudaGetSymbolAddress((void**)&xz,   g_xz);
    cudaGetSymbolAddress((void**)&xc,   g_xc);
    cudaGetSymbolAddress((void**)&dbl,  g_dbl);
    cudaGetSymbolAddress((void**)&dblp, g_dblp);
    cudaGetSymbolAddress((void**)&dtb,  g_dt);
    cudaGetSymbolAddress((void**)&yb,   g_y);
    cudaGetSymbolAddress((void**)&xr,   g_xr);
    cudaGetSymbolAddress((void**)&wa,   g_wa);
    cudaGetSymbolAddress((void**)&wb,   g_wb);
    cudaGetSymbolAddress((void**)&P,    g_P);
    cudaGetSymbolAddress((void**)&Q,    g_Q);
    cudaGetSymbolAddress((void**)&HS,   g_HS);

    cudaFuncSetAttribute((const void*)mma_gemm<0,false,false,false,false,true>,
                         cudaFuncAttributeMaxDynamicSharedMemorySize, MMA_SMEM_PERM);
    cudaFuncSetAttribute((const void*)mma_gemm<0,true,true,true,true,false>,
                         cudaFuncAttributeMaxDynamicSharedMemorySize, MMA_SMEM_STD);
    cudaFuncSetAttribute((const void*)mma_gemm<1,false,true,true,false,false>,
                         cudaFuncAttributeMaxDynamicSharedMemorySize, MMA_SMEM_STD);

    // 0) pre-round + permute big GEMM operands
    {
        int n8;
        n8 = MROWS * DMODEL / 8;
        round_perm_kernel<<<(n8 + 255)/256, 256>>>((const float4*)x, (float4*)xr, n8);
        n8 = NXZ * DMODEL / 8;
        round_perm_kernel<<<(n8 + 255)/256, 256>>>((const float4*)in_proj_w, (float4*)wa, n8);
        n8 = DMODEL * DINNER / 8;
        round_perm_kernel<<<(n8 + 255)/256, 256>>>((const float4*)out_proj_w, (float4*)wb, n8);
    }

    // 1) xz = x @ in_proj_w^T : M=8192 N=4096 K=1024   (PERM)
    {
        dim3 grid(NXZ/128, MROWS/128);
        mma_gemm<0,false,false,false,false,true><<<grid, 256, MMA_SMEM_PERM>>>(
            xr, wa, xz, nullptr, MROWS, NXZ, DMODEL, DMODEL, DMODEL, NXZ);
    }
    // 2) depthwise conv + silu
    {
        int total = MROWS * DINNER / 4;
        conv_silu_kernel<<<total/256, 256>>>(xz, conv_w, conv_b, xc);
    }
    // 3) dbl = xc @ x_proj_w^T : split-K=4 + reduce
    {
        dim3 grid(1, MROWS/128, XPJ_SPLITK);
        mma_gemm<0,true,true,true,true,false><<<grid, 256, MMA_SMEM_STD>>>(
            xc, x_proj_w, dblp, nullptr, MROWS, NDBL, DINNER/XPJ_SPLITK,
            DINNER, DINNER, NDBL);
        int n4 = MROWS * NDBL / 4;
        reduce_splitk_kernel<<<(n4 + 255)/256, 256>>>(
            (const float4*)dblp, (float4*)dbl, n4, n4);
    }
    // 4) dt = softplus(dbl[:, :64] @ dt_proj_w^T + b)
    {
        dim3 grid(DINNER/128, MROWS/128);
        mma_gemm<1,false,true,true,false,false><<<grid, 256, MMA_SMEM_STD>>>(
            dbl, dt_proj_w, dtb, dt_proj_b, MROWS, DINNER, DTRANK,
            NDBL, DTRANK, DINNER);
    }
    // 5) chunked selective scan + gating (smem-staged; y permuted for out_proj)
    {
        dim3 gridA(DINNER/16, BATCH, NCHUNK);
        scan_chunk_kernel<<<gridA, 256>>>(dtb, dbl, xc, A_log, P, Q);
        scan_fix_kernel<<<NBDN/256, 256>>>(P, Q, HS);
        scan_y_kernel<<<gridA, 256>>>(dtb, dbl, xc, xz, A_log, D_param, HS, yb);
    }
    // 6) out = y @ out_proj_w^T : M=8192 N=1024 K=2048  (PERM)
    {
        dim3 grid(DMODEL/128, MROWS/128);
        mma_gemm<0,false,false,false,false,true><<<grid, 256, MMA_SMEM_PERM>>>(
            yb, wb, out, nullptr, MROWS, DMODEL, DINNER,
            DINNER, DINNER, DMODEL);
    }
}

// round 9
// speedup vs baseline: 2.0234x; 2.0234x over previous
#include <cuda_runtime.h>
#include <math.h>
#include <stdint.h>

// Problem constants
#define BATCH   4
#define SEQ     2048
#define DMODEL  1024
#define DINNER  2048
#define DSTATE  16
#define DTRANK  64
#define DCONV   4
#define MROWS   (BATCH*SEQ)          // 8192
#define NXZ     (2*DINNER)           // 4096
#define NDBL    (DTRANK + 2*DSTATE)  // 96
#define NCHUNK  32
#define LCHUNK  (SEQ/NCHUNK)         // 64
#define XPJ_SPLITK 4
#define NBDN    (BATCH*DINNER*DSTATE)    // 131072

// ----------------------------------------------------------------------------
// Scratch (device globals; no runtime allocation allowed)
// ----------------------------------------------------------------------------
__device__ float g_xz [(size_t)MROWS * NXZ];
__device__ float g_xc [(size_t)MROWS * DINNER];
__device__ float g_dbl[(size_t)MROWS * NDBL];
__device__ float g_dblp[(size_t)XPJ_SPLITK * MROWS * NDBL];
__device__ float g_dt [(size_t)MROWS * DINNER];
__device__ float g_y  [(size_t)MROWS * DINNER];   // tf32-rounded
__device__ float g_xr [(size_t)MROWS * DMODEL];   // tf32-rounded x
__device__ float g_wa [(size_t)NXZ   * DMODEL];   // tf32-rounded in_proj_w
__device__ float g_wb [(size_t)DMODEL* DINNER];   // tf32-rounded out_proj_w
// chunked-scan state, layout [chunk][b*d*n]
#define SCAN_ST ((size_t)NCHUNK * NBDN)
__device__ float g_P [SCAN_ST];
__device__ float g_Q [SCAN_ST];
__device__ float g_HS[SCAN_ST];

// ============================================================================
// mma.sync tf32 helpers
// ============================================================================
__device__ __forceinline__ uint32_t f2tf32(float x) {
    uint32_t r;
    asm("cvt.rna.tf32.f32 %0, %1;" : "=r"(r) : "f"(x));
    return r;
}
__device__ __forceinline__ float rtf(float x) {
    return __uint_as_float(f2tf32(x));
}
__device__ __forceinline__ void mma_tf32(float* c, const uint32_t* a, const uint32_t* b) {
    asm volatile(
        "mma.sync.aligned.m16n8k8.row.col.f32.tf32.tf32.f32 "
        "{%0,%1,%2,%3}, {%4,%5,%6,%7}, {%8,%9}, {%0,%1,%2,%3};"
        : "+f"(c[0]), "+f"(c[1]), "+f"(c[2]), "+f"(c[3])
        : "r"(a[0]), "r"(a[1]), "r"(a[2]), "r"(a[3]), "r"(b[0]), "r"(b[1]));
}
__device__ __forceinline__ uint32_t smem_u32(const void* p) {
    uint32_t a;
    asm("{ .reg .u64 t; cvta.to.shared.u64 t, %1; cvt.u32.u64 %0, t; }"
        : "=r"(a) : "l"(p));
    return a;
}
__device__ __forceinline__ void cp_async16(uint32_t dst, const void* src) {
    asm volatile("cp.async.ca.shared.global [%0], [%1], 16;"
                 :: "r"(dst), "l"(src) : "memory");
}
__device__ __forceinline__ void cp_async16z(uint32_t dst, const void* src, bool valid) {
    uint32_t sz = valid ? 16u : 0u;
    asm volatile("cp.async.ca.shared.global [%0], [%1], 16, %2;"
                 :: "r"(dst), "l"(src), "r"(sz) : "memory");
}
#define CP_COMMIT() asm volatile("cp.async.commit_group;" ::: "memory")
#define CP_WAIT(n)  asm volatile("cp.async.wait_group %0;" :: "n"(n) : "memory")

// ============================================================================
// tf32 MMA NT GEMM (round-6 proven config): C[M,N] = A[M,K]*B[N,K]^T.
// CTA 128x128x32, 256 thr, warp tile 64x32, 2-stage cp.async, stride 36.
// ============================================================================
#define MMA_STRIDE   36
#define MMA_STAGE_F  (128 * MMA_STRIDE)
#define MMA_STAGE_B  (MMA_STAGE_F * 4)
#define MMA_SMEM_B   (4 * MMA_STAGE_B)           // 73728 bytes

template<int EPI, bool NGUARD, bool CVTA, bool CVTB, bool SPLITK>
__global__ void __launch_bounds__(256, 2)
mma_gemm(const float* __restrict__ A, const float* __restrict__ B,
         float* __restrict__ C, const float* __restrict__ bias,
         int M, int N, int K, int lda, int ldb, int ldc)
{
    extern __shared__ float sm[];
    const uint32_t smB = smem_u32(sm);

    if (SPLITK) {
        const int z = blockIdx.z;
        A += (size_t)z * K;
        B += (size_t)z * K;
        C += (size_t)z * M * (size_t)ldc;
    }

    const int tid    = threadIdx.x;
    const int lane   = tid & 31;
    const int wid    = tid >> 5;
    const int warp_m = wid >> 2;
    const int warp_n = wid & 3;
    const int lr     = lane >> 2;
    const int lc     = lane & 3;

    const int rowBase = blockIdx.y * 128;
    const int colBase = blockIdx.x * 128;

    float acc[4][4][4];
#pragma unroll
    for (int mt = 0; mt < 4; ++mt)
#pragma unroll
        for (int nt = 0; nt < 4; ++nt)
#pragma unroll
            for (int i = 0; i < 4; ++i) acc[mt][nt][i] = 0.f;

    const int T = K >> 5;

    auto load_stage = [&](int s, int kt) {
        const int kOff = kt << 5;
        const uint32_t aB = smB + s * MMA_STAGE_B;
        const uint32_t bB = smB + 2 * MMA_STAGE_B + s * MMA_STAGE_B;
#pragma unroll
        for (int i = 0; i < 4; ++i) {
            const int chunk = tid + (i << 8);
            const int row = chunk >> 3;
            const int c4  = chunk & 7;
            const uint32_t so = row * (MMA_STRIDE * 4) + c4 * 16;
            cp_async16(aB + so, &A[(size_t)(rowBase + row) * lda + kOff + c4 * 4]);
            if (NGUARD) {
                const bool ok = (colBase + row) < N;
                const int  br = ok ? (colBase + row) : 0;
                cp_async16z(bB + so, &B[(size_t)br * ldb + kOff + c4 * 4], ok);
            } else {
                cp_async16(bB + so, &B[(size_t)(colBase + row) * ldb + kOff + c4 * 4]);
            }
        }
        CP_COMMIT();
    };

    auto fragA = [&](const float* p) -> uint32_t {
        return CVTA ? f2tf32(*p) : __float_as_uint(*p);
    };
    auto fragB = [&](const float* p) -> uint32_t {
        return CVTB ? f2tf32(*p) : __float_as_uint(*p);
    };

    load_stage(0, 0);

    for (int kt = 0; kt < T; ++kt) {
        const int s = kt & 1;
        if (kt + 1 < T) {
            load_stage(s ^ 1, kt + 1);
            CP_WAIT(1);
        } else {
            CP_WAIT(0);
        }
        __syncthreads();

        const float* As_ = sm + s * MMA_STAGE_F;
        const float* Bs_ = sm + 2 * MMA_STAGE_F + s * MMA_STAGE_F;

#pragma unroll
        for (int kk = 0; kk < 4; ++kk) {
            const int k0 = (kk << 3) + lc;
            uint32_t af[4][4];
#pragma unroll
            for (int mt = 0; mt < 4; ++mt) {
                const float* p = As_ + (warp_m * 64 + mt * 16 + lr) * MMA_STRIDE + k0;
                af[mt][0] = fragA(p);
                af[mt][1] = fragA(p + 8 * MMA_STRIDE);
                af[mt][2] = fragA(p + 4);
                af[mt][3] = fragA(p + 8 * MMA_STRIDE + 4);
            }
            uint32_t bf[4][2];
#pragma unroll
            for (int nt = 0; nt < 4; ++nt) {
                const float* p = Bs_ + (warp_n * 32 + nt * 8 + lr) * MMA_STRIDE + k0;
                bf[nt][0] = fragB(p);
                bf[nt][1] = fragB(p + 4);
            }
#pragma unroll
            for (int mt = 0; mt < 4; ++mt)
#pragma unroll
                for (int nt = 0; nt < 4; ++nt)
                    mma_tf32(acc[mt][nt], af[mt], bf[nt]);
        }
        __syncthreads();
    }

#pragma unroll
    for (int mt = 0; mt < 4; ++mt) {
        const int row = rowBase + warp_m * 64 + mt * 16 + lr;
#pragma unroll
        for (int nt = 0; nt < 4; ++nt) {
            const int col = colBase + warp_n * 32 + nt * 8 + 2 * lc;
            if (NGUARD && col >= N) continue;
            float v[4] = {acc[mt][nt][0], acc[mt][nt][1],
                          acc[mt][nt][2], acc[mt][nt][3]};
            if (EPI == 1) {
                const float b0 = bias[col], b1 = bias[col + 1];
                v[0] += b0; v[1] += b1; v[2] += b0; v[3] += b1;
#pragma unroll
                for (int i = 0; i < 4; ++i)
                    v[i] = fmaxf(v[i], 0.f) + log1pf(__expf(-fabsf(v[i])));
            }
            *reinterpret_cast<float2*>(&C[(size_t)row * ldc + col]) =
                make_float2(v[0], v[1]);
            *reinterpret_cast<float2*>(&C[(size_t)(row + 8) * ldc + col]) =
                make_float2(v[2], v[3]);
        }
    }
}

// ----------------------------------------------------------------------------
// split-K reduce
// ----------------------------------------------------------------------------
__global__ void reduce_splitk_kernel(const float4* __restrict__ part,
                                     float4* __restrict__ out, int n4, int stride4)
{
    int i = blockIdx.x * blockDim.x + threadIdx.x;
    if (i < n4) {
        float4 a = part[i];
        float4 b = part[i + stride4];
        float4 c = part[i + 2 * stride4];
        float4 d = part[i + 3 * stride4];
        out[i] = make_float4(a.x + b.x + c.x + d.x, a.y + b.y + c.y + d.y,
                             a.z + b.z + c.z + d.z, a.w + b.w + c.w + d.w);
    }
}

// ----------------------------------------------------------------------------
// Round fp32 array to tf32 (rna)
// ----------------------------------------------------------------------------
__global__ void round_tf32_kernel(const float4* __restrict__ in,
                                  float4* __restrict__ out, int n4)
{
    int i = blockIdx.x * blockDim.x + threadIdx.x;
    if (i < n4) {
        float4 v = in[i];
        v.x = rtf(v.x); v.y = rtf(v.y); v.z = rtf(v.z); v.w = rtf(v.w);
        out[i] = v;
    }
}

// ----------------------------------------------------------------------------
// Depthwise causal conv (width 4) + SiLU — float4 over channels
// ----------------------------------------------------------------------------
__global__ void conv_silu_kernel(const float* __restrict__ xz,
                                 const float* __restrict__ w,
                                 const float* __restrict__ b,
                                 float* __restrict__ xc)
{
    int i = blockIdx.x * blockDim.x + threadIdx.x;
    int d4 = (i & 511) << 2;
    int m  = i >> 9;
    int l  = m & (SEQ - 1);

    float4 wv[4];
#pragma unroll
    for (int c = 0; c < 4; ++c)
        wv[c] = *reinterpret_cast<const float4*>(&w[(d4 + c) * DCONV]);
    float4 acc = *reinterpret_cast<const float4*>(&b[d4]);

#pragma unroll
    for (int j = 0; j < DCONV; ++j) {
        int lj = l - (DCONV - 1) + j;
        if (lj >= 0) {
            float4 xv = *reinterpret_cast<const float4*>(
                &xz[(size_t)(m - (DCONV - 1) + j) * NXZ + d4]);
            acc.x = fmaf(((const float*)&wv[0])[j], xv.x, acc.x);
            acc.y = fmaf(((const float*)&wv[1])[j], xv.y, acc.y);
            acc.z = fmaf(((const float*)&wv[2])[j], xv.z, acc.z);
            acc.w = fmaf(((const float*)&wv[3])[j], xv.w, acc.w);
        }
    }
    acc.x = acc.x / (1.f + __expf(-acc.x));
    acc.y = acc.y / (1.f + __expf(-acc.y));
    acc.z = acc.z / (1.f + __expf(-acc.z));
    acc.w = acc.w / (1.f + __expf(-acc.w));
    *reinterpret_cast<float4*>(&xc[(size_t)m * DINNER + d4]) = acc;
}

// ============================================================================
// Chunked selective scan v2: 2 states per lane, 4 channels per warp.
// Block = 32 channels x 64 steps, 256 threads.
// Lane map: npair = lane&7 (n = 2*npair, 2*npair+1), dloc = warp*4 + (lane>>3).
// State arrays: [chunk][ (b*DINNER+d)*16 + n ].
// ============================================================================
#define SCAN_D 32

// Pass A: per-chunk (P, Q) with h0 = 0.
__global__ void __launch_bounds__(256) scan_chunk_kernel(
    const float* __restrict__ dt,  const float* __restrict__ dbl,
    const float* __restrict__ xc,  const float* __restrict__ A_log,
    float* __restrict__ P, float* __restrict__ Q)
{
    __shared__ float s_dt [LCHUNK * SCAN_D];
    __shared__ float s_dtx[LCHUNK * SCAN_D];
    __shared__ float s_B  [LCHUNK * 16];

    const int tid  = threadIdx.x;
    const int d0   = blockIdx.x * SCAN_D;
    const int b    = blockIdx.y;
    const int c    = blockIdx.z;
    const int m0   = b * SEQ + c * LCHUNK;

    // stage dt, dtx = dt*xc (rows 0..63 x 32 cols), B (rows x 16)
    {
        const int trow = tid >> 3;              // 0..31
        const int tc4  = (tid & 7) << 2;        // 0..28
#pragma unroll
        for (int r = trow; r < LCHUNK; r += 32) {
            const size_t gm = (size_t)(m0 + r);
            float4 vdt = *reinterpret_cast<const float4*>(&dt[gm * DINNER + d0 + tc4]);
            float4 vxc = *reinterpret_cast<const float4*>(&xc[gm * DINNER + d0 + tc4]);
            *reinterpret_cast<float4*>(&s_dt[r * SCAN_D + tc4]) = vdt;
            float4 vp = make_float4(vdt.x * vxc.x, vdt.y * vxc.y,
                                    vdt.z * vxc.z, vdt.w * vxc.w);
            *reinterpret_cast<float4*>(&s_dtx[r * SCAN_D + tc4]) = vp;
        }
        const int trB = tid >> 2;               // 0..63
        const int tcB = (tid & 3) << 2;         // 0..12
        *reinterpret_cast<float4*>(&s_B[trB * 16 + tcB]) =
            *reinterpret_cast<const float4*>(&dbl[(size_t)(m0 + trB) * NDBL + DTRANK + tcB]);
    }
    __syncthreads();

    const int lane  = tid & 31;
    const int warp  = tid >> 5;
    const int npair = lane & 7;
    const int dloc  = warp * 4 + (lane >> 3);
    const int d     = d0 + dloc;
    const int n0    = npair << 1;

    const float Ad0 = -__expf(A_log[d * DSTATE + n0]);
    const float Ad1 = -__expf(A_log[d * DSTATE + n0 + 1]);
    float P0 = 1.f, P1 = 1.f, h0 = 0.f, h1 = 0.f;

#pragma unroll 4
    for (int l = 0; l < LCHUNK; ++l) {
        const float dtv = s_dt [l * SCAN_D + dloc];
        const float ux  = s_dtx[l * SCAN_D + dloc];
        const float2 B2 = *reinterpret_cast<const float2*>(&s_B[l * 16 + n0]);
        const float e0 = __expf(dtv * Ad0);
        const float e1 = __expf(dtv * Ad1);
        P0 *= e0; P1 *= e1;
        h0 = fmaf(e0, h0, ux * B2.x);
        h1 = fmaf(e1, h1, ux * B2.y);
    }
    const size_t idx = (size_t)c * NBDN + ((size_t)b * DINNER + d) * DSTATE + n0;
    *reinterpret_cast<float2*>(&P[idx]) = make_float2(P0, P1);
    *reinterpret_cast<float2*>(&Q[idx]) = make_float2(h0, h1);
}

// Pass B: compose chunk states serially (coalesced [chunk][i] layout).
__global__ void __launch_bounds__(256) scan_fix_kernel(
    const float* __restrict__ P, const float* __restrict__ Q,
    float* __restrict__ HS)
{
    const size_t i = (size_t)blockIdx.x * blockDim.x + threadIdx.x;
    float h = 0.f;
#pragma unroll
    for (int c = 0; c < NCHUNK; ++c) {
        const size_t k = (size_t)c * NBDN + i;
        HS[k] = h;
        h = fmaf(P[k], h, Q[k]);
    }
}

// Pass C: re-scan from exact start state; gate with silu(z) at store time.
__global__ void __launch_bounds__(256) scan_y_kernel(
    const float* __restrict__ dt,  const float* __restrict__ dbl,
    const float* __restrict__ xc,  const float* __restrict__ xz,
    const float* __restrict__ A_log, const float* __restrict__ Dp,
    const float* __restrict__ HS, float* __restrict__ y)
{
    __shared__ float s_dt [LCHUNK * SCAN_D];
    __shared__ float s_dtx[LCHUNK * SCAN_D];
    __shared__ float s_xc [LCHUNK * SCAN_D];
    __shared__ float s_B  [LCHUNK * 16];
    __shared__ float s_C  [LCHUNK * 16];
    __shared__ float s_y  [LCHUNK * SCAN_D];

    const int tid  = threadIdx.x;
    const int d0   = blockIdx.x * SCAN_D;
    const int b    = blockIdx.y;
    const int c    = blockIdx.z;
    const int m0   = b * SEQ + c * LCHUNK;

    {
        const int trow = tid >> 3;
        const int tc4  = (tid & 7) << 2;
#pragma unroll
        for (int r = trow; r < LCHUNK; r += 32) {
            const size_t gm = (size_t)(m0 + r);
            float4 vdt = *reinterpret_cast<const float4*>(&dt[gm * DINNER + d0 + tc4]);
            float4 vxc = *reinterpret_cast<const float4*>(&xc[gm * DINNER + d0 + tc4]);
            *reinterpret_cast<float4*>(&s_dt[r * SCAN_D + tc4]) = vdt;
            *reinterpret_cast<float4*>(&s_xc[r * SCAN_D + tc4]) = vxc;
            float4 vp = make_float4(vdt.x * vxc.x, vdt.y * vxc.y,
                                    vdt.z * vxc.z, vdt.w * vxc.w);
            *reinterpret_cast<float4*>(&s_dtx[r * SCAN_D + tc4]) = vp;
        }
        const int trB = tid >> 2;
        const int tcB = (tid & 3) << 2;
        *reinterpret_cast<float4*>(&s_B[trB * 16 + tcB]) =
            *reinterpret_cast<const float4*>(&dbl[(size_t)(m0 + trB) * NDBL + DTRANK + tcB]);
        *reinterpret_cast<float4*>(&s_C[trB * 16 + tcB]) =
            *reinterpret_cast<const float4*>(&dbl[(size_t)(m0 + trB) * NDBL + DTRANK + DSTATE + tcB]);
    }
    __syncthreads();

    const int lane  = tid & 31;
    const int warp  = tid >> 5;
    const int npair = lane & 7;
    const int dloc  = warp * 4 + (lane >> 3);
    const int d     = d0 + dloc;
    const int n0    = npair << 1;

    const float Ad0 = -__expf(A_log[d * DSTATE + n0]);
    const float Ad1 = -__expf(A_log[d * DSTATE + n0 + 1]);
    const float Dd  = Dp[d];

    const float2 hs = *reinterpret_cast<const float2*>(
        &HS[(size_t)c * NBDN + ((size_t)b * DINNER + d) * DSTATE + n0]);
    float h0 = hs.x, h1 = hs.y;

#pragma unroll 2
    for (int l = 0; l < LCHUNK; ++l) {
        const float dtv = s_dt [l * SCAN_D + dloc];
        const float ux  = s_dtx[l * SCAN_D + dloc];
        const float2 B2 = *reinterpret_cast<const float2*>(&s_B[l * 16 + n0]);
        const float2 C2 = *reinterpret_cast<const float2*>(&s_C[l * 16 + n0]);
        const float e0 = __expf(dtv * Ad0);
        const float e1 = __expf(dtv * Ad1);
        h0 = fmaf(e0, h0, ux * B2.x);
        h1 = fmaf(e1, h1, ux * B2.y);

        float p = fmaf(h0, C2.x, h1 * C2.y);
        p += __shfl_xor_sync(0xffffffffu, p, 1);
        p += __shfl_xor_sync(0xffffffffu, p, 2);
        p += __shfl_xor_sync(0xffffffffu, p, 4);

        if (npair == 0)
            s_y[l * SCAN_D + dloc] = fmaf(Dd, s_xc[l * SCAN_D + dloc], p);
    }
    __syncthreads();

    // store: gate with silu(z) read directly from global, round to tf32
    {
        const int trow = tid >> 3;
        const int tc4  = (tid & 7) << 2;
#pragma unroll
        for (int r = trow; r < LCHUNK; r += 32) {
            const size_t gm = (size_t)(m0 + r);
            float4 v = *reinterpret_cast<const float4*>(&s_y[r * SCAN_D + tc4]);
            float4 z = *reinterpret_cast<const float4*>(&xz[gm * NXZ + DINNER + d0 + tc4]);
            v.x = rtf(v.x * (z.x / (1.f + __expf(-z.x))));
            v.y = rtf(v.y * (z.y / (1.f + __expf(-z.y))));
            v.z = rtf(v.z * (z.z / (1.f + __expf(-z.z))));
            v.w = rtf(v.w * (z.w / (1.f + __expf(-z.w))));
            *reinterpret_cast<float4*>(&y[gm * DINNER + d0 + tc4]) = v;
        }
    }
}

// ----------------------------------------------------------------------------
// Launch
// ----------------------------------------------------------------------------
extern "C" void kernel_launch(void* const* d_in, const int* in_sizes, int n_in,
                              void* d_out, int out_size)
{
    const float* x          = (const float*)d_in[0];
    const float* in_proj_w  = (const float*)d_in[1];
    const float* conv_w     = (const float*)d_in[2];
    const float* conv_b     = (const float*)d_in[3];
    const float* x_proj_w   = (const float*)d_in[4];
    const float* dt_proj_w  = (const float*)d_in[5];
    const float* dt_proj_b  = (const float*)d_in[6];
    const float* A_log      = (const float*)d_in[7];
    const float* D_param    = (const float*)d_in[8];
    const float* out_proj_w = (const float*)d_in[9];
    float* out = (float*)d_out;

    float *xz, *xc, *dbl, *dblp, *dtb, *yb, *xr, *wa, *wb, *P, *Q, *HS;
    cudaGetSymbolAddress((void**)&xz,   g_xz);
    cudaGetSymbolAddress((void**)&xc,   g_xc);
    cudaGetSymbolAddress((void**)&dbl,  g_dbl);
    cudaGetSymbolAddress((void**)&dblp, g_dblp);
    cudaGetSymbolAddress((void**)&dtb,  g_dt);
    cudaGetSymbolAddress((void**)&yb,   g_y);
    cudaGetSymbolAddress((void**)&xr,   g_xr);
    cudaGetSymbolAddress((void**)&wa,   g_wa);
    cudaGetSymbolAddress((void**)&wb,   g_wb);
    cudaGetSymbolAddress((void**)&P,    g_P);
    cudaGetSymbolAddress((void**)&Q,    g_Q);
    cudaGetSymbolAddress((void**)&HS,   g_HS);

    cudaFuncSetAttribute((const void*)mma_gemm<0,false,false,false,false>,
                         cudaFuncAttributeMaxDynamicSharedMemorySize, MMA_SMEM_B);
    cudaFuncSetAttribute((const void*)mma_gemm<0,true,true,true,true>,
                         cudaFuncAttributeMaxDynamicSharedMemorySize, MMA_SMEM_B);
    cudaFuncSetAttribute((const void*)mma_gemm<1,false,true,true,false>,
                         cudaFuncAttributeMaxDynamicSharedMemorySize, MMA_SMEM_B);

    // 0) pre-round big GEMM operands to tf32
    {
        int n4;
        n4 = MROWS * DMODEL / 4;
        round_tf32_kernel<<<(n4 + 255)/256, 256>>>((const float4*)x, (float4*)xr, n4);
        n4 = NXZ * DMODEL / 4;
        round_tf32_kernel<<<(n4 + 255)/256, 256>>>((const float4*)in_proj_w, (float4*)wa, n4);
        n4 = DMODEL * DINNER / 4;
        round_tf32_kernel<<<(n4 + 255)/256, 256>>>((const float4*)out_proj_w, (float4*)wb, n4);
    }

    // 1) xz = x @ in_proj_w^T : M=8192 N=4096 K=1024
    {
        dim3 grid(NXZ/128, MROWS/128);
        mma_gemm<0,false,false,false,false><<<grid, 256, MMA_SMEM_B>>>(
            xr, wa, xz, nullptr, MROWS, NXZ, DMODEL, DMODEL, DMODEL, NXZ);
    }
    // 2) depthwise conv + silu
    {
        int total = MROWS * DINNER / 4;
        conv_silu_kernel<<<total/256, 256>>>(xz, conv_w, conv_b, xc);
    }
    // 3) dbl = xc @ x_proj_w^T : split-K=4 + reduce
    {
        dim3 grid(1, MROWS/128, XPJ_SPLITK);
        mma_gemm<0,true,true,true,true><<<grid, 256, MMA_SMEM_B>>>(
            xc, x_proj_w, dblp, nullptr, MROWS, NDBL, DINNER/XPJ_SPLITK,
            DINNER, DINNER, NDBL);
        int n4 = MROWS * NDBL / 4;
        reduce_splitk_kernel<<<(n4 + 255)/256, 256>>>(
            (const float4*)dblp, (float4*)dbl, n4, n4);
    }
    // 4) dt = softplus(dbl[:, :64] @ dt_proj_w^T + b)
    {
        dim3 grid(DINNER/128, MROWS/128);
        mma_gemm<1,false,true,true,false><<<grid, 256, MMA_SMEM_B>>>(
            dbl, dt_proj_w, dtb, dt_proj_b, MROWS, DINNER, DTRANK,
            NDBL, DTRANK, DINNER);
    }
    // 5) chunked selective scan + gating (v2: 4 channels/warp)
    {
        dim3 gridA(DINNER/SCAN_D, BATCH, NCHUNK);
        scan_chunk_kernel<<<gridA, 256>>>(dtb, dbl, xc, A_log, P, Q);
        scan_fix_kernel<<<NBDN/256, 256>>>(P, Q, HS);
        scan_y_kernel<<<gridA, 256>>>(dtb, dbl, xc, xz, A_log, D_param, HS, yb);
    }
    // 6) out = y @ out_proj_w^T : M=8192 N=1024 K=2048
    {
        dim3 grid(DMODEL/128, MROWS/128);
        mma_gemm<0,false,false,false,false><<<grid, 256, MMA_SMEM_B>>>(
            yb, wb, out, nullptr, MROWS, DMODEL, DINNER,
            DINNER, DINNER, DMODEL);
    }
}

// round 10
// speedup vs baseline: 2.0251x; 1.0008x over previous
#include <cuda_runtime.h>
#include <math.h>
#include <stdint.h>

// Problem constants
#define BATCH   4
#define SEQ     2048
#define DMODEL  1024
#define DINNER  2048
#define DSTATE  16
#define DTRANK  64
#define DCONV   4
#define MROWS   (BATCH*SEQ)          // 8192
#define NXZ     (2*DINNER)           // 4096
#define NDBL    (DTRANK + 2*DSTATE)  // 96
#define NCHUNK  32
#define LCHUNK  (SEQ/NCHUNK)         // 64
#define XPJ_SPLITK 4
#define NBDN    (BATCH*DINNER*DSTATE)    // 131072

// ----------------------------------------------------------------------------
// Scratch (device globals; no runtime allocation allowed)
// ----------------------------------------------------------------------------
__device__ float g_xz [(size_t)MROWS * NXZ];
__device__ float g_xc [(size_t)MROWS * DINNER];
__device__ float g_dbl[(size_t)MROWS * NDBL];
__device__ float g_dblp[(size_t)XPJ_SPLITK * MROWS * NDBL];
__device__ float g_dt [(size_t)MROWS * DINNER];
__device__ float g_y  [(size_t)MROWS * DINNER];   // tf32-rounded
__device__ float g_xr [(size_t)MROWS * DMODEL];   // tf32-rounded x
__device__ float g_wa [(size_t)NXZ   * DMODEL];   // tf32-rounded in_proj_w
__device__ float g_wb [(size_t)DMODEL* DINNER];   // tf32-rounded out_proj_w
// chunked-scan state, layout [chunk][b*d*n]
#define SCAN_ST ((size_t)NCHUNK * NBDN)
__device__ float g_P [SCAN_ST];
__device__ float g_Q [SCAN_ST];
__device__ float g_HS[SCAN_ST];

// ============================================================================
// mma.sync tf32 helpers
// ============================================================================
__device__ __forceinline__ uint32_t f2tf32(float x) {
    uint32_t r;
    asm("cvt.rna.tf32.f32 %0, %1;" : "=r"(r) : "f"(x));
    return r;
}
__device__ __forceinline__ float rtf(float x) {
    return __uint_as_float(f2tf32(x));
}
__device__ __forceinline__ void mma_tf32(float* c, const uint32_t* a, const uint32_t* b) {
    asm volatile(
        "mma.sync.aligned.m16n8k8.row.col.f32.tf32.tf32.f32 "
        "{%0,%1,%2,%3}, {%4,%5,%6,%7}, {%8,%9}, {%0,%1,%2,%3};"
        : "+f"(c[0]), "+f"(c[1]), "+f"(c[2]), "+f"(c[3])
        : "r"(a[0]), "r"(a[1]), "r"(a[2]), "r"(a[3]), "r"(b[0]), "r"(b[1]));
}
__device__ __forceinline__ uint32_t smem_u32(const void* p) {
    uint32_t a;
    asm("{ .reg .u64 t; cvta.to.shared.u64 t, %1; cvt.u32.u64 %0, t; }"
        : "=r"(a) : "l"(p));
    return a;
}
__device__ __forceinline__ void cp_async16(uint32_t dst, const void* src) {
    asm volatile("cp.async.cg.shared.global [%0], [%1], 16;"
                 :: "r"(dst), "l"(src) : "memory");
}
__device__ __forceinline__ void cp_async16z(uint32_t dst, const void* src, bool valid) {
    uint32_t sz = valid ? 16u : 0u;
    asm volatile("cp.async.cg.shared.global [%0], [%1], 16, %2;"
                 :: "r"(dst), "l"(src), "r"(sz) : "memory");
}
#define CP_COMMIT() asm volatile("cp.async.commit_group;" ::: "memory")
#define CP_WAIT(n)  asm volatile("cp.async.wait_group %0;" :: "n"(n) : "memory")

// ============================================================================
// tf32 MMA NT GEMM (round-6 proven config): C[M,N] = A[M,K]*B[N,K]^T.
// CTA 128x128x32, 256 thr, warp tile 64x32, 2-stage cp.async, stride 36.
// ============================================================================
#define MMA_STRIDE   36
#define MMA_STAGE_F  (128 * MMA_STRIDE)
#define MMA_STAGE_B  (MMA_STAGE_F * 4)
#define MMA_SMEM_B   (4 * MMA_STAGE_B)           // 73728 bytes

template<int EPI, bool NGUARD, bool CVTA, bool CVTB, bool SPLITK>
__global__ void __launch_bounds__(256, 2)
mma_gemm(const float* __restrict__ A, const float* __restrict__ B,
         float* __restrict__ C, const float* __restrict__ bias,
         int M, int N, int K, int lda, int ldb, int ldc)
{
    extern __shared__ float sm[];
    const uint32_t smB = smem_u32(sm);

    if (SPLITK) {
        const int z = blockIdx.z;
        A += (size_t)z * K;
        B += (size_t)z * K;
        C += (size_t)z * M * (size_t)ldc;
    }

    const int tid    = threadIdx.x;
    const int lane   = tid & 31;
    const int wid    = tid >> 5;
    const int warp_m = wid >> 2;
    const int warp_n = wid & 3;
    const int lr     = lane >> 2;
    const int lc     = lane & 3;

    const int rowBase = blockIdx.y * 128;
    const int colBase = blockIdx.x * 128;

    float acc[4][4][4];
#pragma unroll
    for (int mt = 0; mt < 4; ++mt)
#pragma unroll
        for (int nt = 0; nt < 4; ++nt)
#pragma unroll
            for (int i = 0; i < 4; ++i) acc[mt][nt][i] = 0.f;

    const int T = K >> 5;

    auto load_stage = [&](int s, int kt) {
        const int kOff = kt << 5;
        const uint32_t aB = smB + s * MMA_STAGE_B;
        const uint32_t bB = smB + 2 * MMA_STAGE_B + s * MMA_STAGE_B;
#pragma unroll
        for (int i = 0; i < 4; ++i) {
            const int chunk = tid + (i << 8);
            const int row = chunk >> 3;
            const int c4  = chunk & 7;
            const uint32_t so = row * (MMA_STRIDE * 4) + c4 * 16;
            cp_async16(aB + so, &A[(size_t)(rowBase + row) * lda + kOff + c4 * 4]);
            if (NGUARD) {
                const bool ok = (colBase + row) < N;
                const int  br = ok ? (colBase + row) : 0;
                cp_async16z(bB + so, &B[(size_t)br * ldb + kOff + c4 * 4], ok);
            } else {
                cp_async16(bB + so, &B[(size_t)(colBase + row) * ldb + kOff + c4 * 4]);
            }
        }
        CP_COMMIT();
    };

    auto fragA = [&](const float* p) -> uint32_t {
        return CVTA ? f2tf32(*p) : __float_as_uint(*p);
    };
    auto fragB = [&](const float* p) -> uint32_t {
        return CVTB ? f2tf32(*p) : __float_as_uint(*p);
    };

    load_stage(0, 0);

    for (int kt = 0; kt < T; ++kt) {
        const int s = kt & 1;
        if (kt + 1 < T) {
            load_stage(s ^ 1, kt + 1);
            CP_WAIT(1);
        } else {
            CP_WAIT(0);
        }
        __syncthreads();

        const float* As_ = sm + s * MMA_STAGE_F;
        const float* Bs_ = sm + 2 * MMA_STAGE_F + s * MMA_STAGE_F;

#pragma unroll
        for (int kk = 0; kk < 4; ++kk) {
            const int k0 = (kk << 3) + lc;
            uint32_t af[4][4];
#pragma unroll
            for (int mt = 0; mt < 4; ++mt) {
                const float* p = As_ + (warp_m * 64 + mt * 16 + lr) * MMA_STRIDE + k0;
                af[mt][0] = fragA(p);
                af[mt][1] = fragA(p + 8 * MMA_STRIDE);
                af[mt][2] = fragA(p + 4);
                af[mt][3] = fragA(p + 8 * MMA_STRIDE + 4);
            }
            uint32_t bf[4][2];
#pragma unroll
            for (int nt = 0; nt < 4; ++nt) {
                const float* p = Bs_ + (warp_n * 32 + nt * 8 + lr) * MMA_STRIDE + k0;
                bf[nt][0] = fragB(p);
                bf[nt][1] = fragB(p + 4);
            }
#pragma unroll
            for (int mt = 0; mt < 4; ++mt)
#pragma unroll
                for (int nt = 0; nt < 4; ++nt)
                    mma_tf32(acc[mt][nt], af[mt], bf[nt]);
        }
        __syncthreads();
    }

#pragma unroll
    for (int mt = 0; mt < 4; ++mt) {
        const int row = rowBase + warp_m * 64 + mt * 16 + lr;
#pragma unroll
        for (int nt = 0; nt < 4; ++nt) {
            const int col = colBase + warp_n * 32 + nt * 8 + 2 * lc;
            if (NGUARD && col >= N) continue;
            float v[4] = {acc[mt][nt][0], acc[mt][nt][1],
                          acc[mt][nt][2], acc[mt][nt][3]};
            if (EPI == 1) {
                const float b0 = bias[col], b1 = bias[col + 1];
                v[0] += b0; v[1] += b1; v[2] += b0; v[3] += b1;
#pragma unroll
                for (int i = 0; i < 4; ++i)
                    v[i] = fmaxf(v[i], 0.f) + log1pf(__expf(-fabsf(v[i])));
            }
            *reinterpret_cast<float2*>(&C[(size_t)row * ldc + col]) =
                make_float2(v[0], v[1]);
            *reinterpret_cast<float2*>(&C[(size_t)(row + 8) * ldc + col]) =
                make_float2(v[2], v[3]);
        }
    }
}

// ----------------------------------------------------------------------------
// split-K reduce
// ----------------------------------------------------------------------------
__global__ void reduce_splitk_kernel(const float4* __restrict__ part,
                                     float4* __restrict__ out, int n4, int stride4)
{
    int i = blockIdx.x * blockDim.x + threadIdx.x;
    if (i < n4) {
        float4 a = part[i];
        float4 b = part[i + stride4];
        float4 c = part[i + 2 * stride4];
        float4 d = part[i + 3 * stride4];
        out[i] = make_float4(a.x + b.x + c.x + d.x, a.y + b.y + c.y + d.y,
                             a.z + b.z + c.z + d.z, a.w + b.w + c.w + d.w);
    }
}

// ----------------------------------------------------------------------------
// Round three fp32 arrays to tf32 (rna) in one launch.
// Segments: [0,n0) -> (inA,outA), [n0,n0+n1) -> (inB,outB), rest -> (inC,outC)
// ----------------------------------------------------------------------------
__global__ void round3_tf32_kernel(const float4* __restrict__ inA, float4* __restrict__ outA, int n0,
                                   const float4* __restrict__ inB, float4* __restrict__ outB, int n1,
                                   const float4* __restrict__ inC, float4* __restrict__ outC, int n2)
{
    int i = blockIdx.x * blockDim.x + threadIdx.x;
    const float4* in;
    float4* out;
    int j;
    if (i < n0)            { in = inA; out = outA; j = i; }
    else if (i < n0 + n1)  { in = inB; out = outB; j = i - n0; }
    else if (i < n0+n1+n2) { in = inC; out = outC; j = i - n0 - n1; }
    else return;
    float4 v = in[j];
    v.x = rtf(v.x); v.y = rtf(v.y); v.z = rtf(v.z); v.w = rtf(v.w);
    out[j] = v;
}

// ----------------------------------------------------------------------------
// Depthwise causal conv (width 4) + SiLU — float4 over channels
// ----------------------------------------------------------------------------
__global__ void conv_silu_kernel(const float* __restrict__ xz,
                                 const float* __restrict__ w,
                                 const float* __restrict__ b,
                                 float* __restrict__ xc)
{
    int i = blockIdx.x * blockDim.x + threadIdx.x;
    int d4 = (i & 511) << 2;
    int m  = i >> 9;
    int l  = m & (SEQ - 1);

    float4 wv[4];
#pragma unroll
    for (int c = 0; c < 4; ++c)
        wv[c] = *reinterpret_cast<const float4*>(&w[(d4 + c) * DCONV]);
    float4 acc = *reinterpret_cast<const float4*>(&b[d4]);

#pragma unroll
    for (int j = 0; j < DCONV; ++j) {
        int lj = l - (DCONV - 1) + j;
        if (lj >= 0) {
            float4 xv = *reinterpret_cast<const float4*>(
                &xz[(size_t)(m - (DCONV - 1) + j) * NXZ + d4]);
            acc.x = fmaf(((const float*)&wv[0])[j], xv.x, acc.x);
            acc.y = fmaf(((const float*)&wv[1])[j], xv.y, acc.y);
            acc.z = fmaf(((const float*)&wv[2])[j], xv.z, acc.z);
            acc.w = fmaf(((const float*)&wv[3])[j], xv.w, acc.w);
        }
    }
    acc.x = acc.x / (1.f + __expf(-acc.x));
    acc.y = acc.y / (1.f + __expf(-acc.y));
    acc.z = acc.z / (1.f + __expf(-acc.z));
    acc.w = acc.w / (1.f + __expf(-acc.w));
    *reinterpret_cast<float4*>(&xc[(size_t)m * DINNER + d4]) = acc;
}

// ============================================================================
// Chunked selective scan v3: 2 states/lane, 4 channels/warp, packed smem.
// Block = 32 channels x 64 steps, 256 threads.
// s_dd[l][dloc] = float2{dt, dt*xc}  (one LDS.64 per step)
// s_BC[l][npair] = float4{B0,B1,C0,C1} (one LDS.128 per step, pass C)
// ============================================================================
#define SCAN_D 32

// Pass A: per-chunk (P, Q) with h0 = 0.
__global__ void __launch_bounds__(256) scan_chunk_kernel(
    const float* __restrict__ dt,  const float* __restrict__ dbl,
    const float* __restrict__ xc,  const float* __restrict__ A_log,
    float* __restrict__ P, float* __restrict__ Q)
{
    __shared__ float s_dd[LCHUNK * SCAN_D * 2];   // {dt, dtx} pairs
    __shared__ float s_B [LCHUNK * 16];

    const int tid  = threadIdx.x;
    const int d0   = blockIdx.x * SCAN_D;
    const int b    = blockIdx.y;
    const int c    = blockIdx.z;
    const int m0   = b * SEQ + c * LCHUNK;

    {
        const int trow = tid >> 3;              // 0..31
        const int tc4  = (tid & 7) << 2;        // 0..28
#pragma unroll
        for (int r = trow; r < LCHUNK; r += 32) {
            const size_t gm = (size_t)(m0 + r);
            float4 vdt = *reinterpret_cast<const float4*>(&dt[gm * DINNER + d0 + tc4]);
            float4 vxc = *reinterpret_cast<const float4*>(&xc[gm * DINNER + d0 + tc4]);
            float* dst = &s_dd[(r * SCAN_D + tc4) * 2];
            *reinterpret_cast<float4*>(dst) =
                make_float4(vdt.x, vdt.x * vxc.x, vdt.y, vdt.y * vxc.y);
            *reinterpret_cast<float4*>(dst + 4) =
                make_float4(vdt.z, vdt.z * vxc.z, vdt.w, vdt.w * vxc.w);
        }
        const int trB = tid >> 2;               // 0..63
        const int tcB = (tid & 3) << 2;         // 0..12
        *reinterpret_cast<float4*>(&s_B[trB * 16 + tcB]) =
            *reinterpret_cast<const float4*>(&dbl[(size_t)(m0 + trB) * NDBL + DTRANK + tcB]);
    }
    __syncthreads();

    const int lane  = tid & 31;
    const int warp  = tid >> 5;
    const int npair = lane & 7;
    const int dloc  = warp * 4 + (lane >> 3);
    const int d     = d0 + dloc;
    const int n0    = npair << 1;

    const float Ad0 = -__expf(A_log[d * DSTATE + n0]);
    const float Ad1 = -__expf(A_log[d * DSTATE + n0 + 1]);
    float P0 = 1.f, P1 = 1.f, h0 = 0.f, h1 = 0.f;

#pragma unroll 4
    for (int l = 0; l < LCHUNK; ++l) {
        const float2 dd = *reinterpret_cast<const float2*>(&s_dd[(l * SCAN_D + dloc) * 2]);
        const float2 B2 = *reinterpret_cast<const float2*>(&s_B[l * 16 + n0]);
        const float e0 = __expf(dd.x * Ad0);
        const float e1 = __expf(dd.x * Ad1);
        P0 *= e0; P1 *= e1;
        h0 = fmaf(e0, h0, dd.y * B2.x);
        h1 = fmaf(e1, h1, dd.y * B2.y);
    }
    const size_t idx = (size_t)c * NBDN + ((size_t)b * DINNER + d) * DSTATE + n0;
    *reinterpret_cast<float2*>(&P[idx]) = make_float2(P0, P1);
    *reinterpret_cast<float2*>(&Q[idx]) = make_float2(h0, h1);
}

// Pass B: compose chunk states serially (coalesced [chunk][i] layout).
__global__ void __launch_bounds__(256) scan_fix_kernel(
    const float* __restrict__ P, const float* __restrict__ Q,
    float* __restrict__ HS)
{
    const size_t i = (size_t)blockIdx.x * blockDim.x + threadIdx.x;
    float h = 0.f;
#pragma unroll
    for (int c = 0; c < NCHUNK; ++c) {
        const size_t k = (size_t)c * NBDN + i;
        HS[k] = h;
        h = fmaf(P[k], h, Q[k]);
    }
}

// Pass C: re-scan from exact start state; silu(z) precomputed in registers.
__global__ void __launch_bounds__(256) scan_y_kernel(
    const float* __restrict__ dt,  const float* __restrict__ dbl,
    const float* __restrict__ xc,  const float* __restrict__ xz,
    const float* __restrict__ A_log, const float* __restrict__ Dp,
    const float* __restrict__ HS, float* __restrict__ y)
{
    __shared__ float s_dd[LCHUNK * SCAN_D * 2];   // {dt, dtx}
    __shared__ float s_xc[LCHUNK * SCAN_D];
    __shared__ float s_BC[LCHUNK * 32];           // {B0,B1,C0,C1} per npair
    __shared__ float s_y [LCHUNK * SCAN_D];

    const int tid  = threadIdx.x;
    const int d0   = blockIdx.x * SCAN_D;
    const int b    = blockIdx.y;
    const int c    = blockIdx.z;
    const int m0   = b * SEQ + c * LCHUNK;

    const int trow = tid >> 3;              // 0..31
    const int tc4  = (tid & 7) << 2;        // 0..28
    float4 zs[2];                           // pre-silu'd gate values

    {
#pragma unroll
        for (int rr = 0; rr < 2; ++rr) {
            const int r = trow + rr * 32;
            const size_t gm = (size_t)(m0 + r);
            float4 vdt = *reinterpret_cast<const float4*>(&dt[gm * DINNER + d0 + tc4]);
            float4 vxc = *reinterpret_cast<const float4*>(&xc[gm * DINNER + d0 + tc4]);
            float4 vz  = *reinterpret_cast<const float4*>(&xz[gm * NXZ + DINNER + d0 + tc4]);
            *reinterpret_cast<float4*>(&s_xc[r * SCAN_D + tc4]) = vxc;
            float* dst = &s_dd[(r * SCAN_D + tc4) * 2];
            *reinterpret_cast<float4*>(dst) =
                make_float4(vdt.x, vdt.x * vxc.x, vdt.y, vdt.y * vxc.y);
            *reinterpret_cast<float4*>(dst + 4) =
                make_float4(vdt.z, vdt.z * vxc.z, vdt.w, vdt.w * vxc.w);
            vz.x = vz.x / (1.f + __expf(-vz.x));
            vz.y = vz.y / (1.f + __expf(-vz.y));
            vz.z = vz.z / (1.f + __expf(-vz.z));
            vz.w = vz.w / (1.f + __expf(-vz.w));
            zs[rr] = vz;
        }
        const int trB = tid >> 2;           // 0..63
        const int tcB = (tid & 3) << 2;     // n = tcB..tcB+3 -> npair tcB/2, tcB/2+1
        float4 vB = *reinterpret_cast<const float4*>(&dbl[(size_t)(m0 + trB) * NDBL + DTRANK + tcB]);
        float4 vC = *reinterpret_cast<const float4*>(&dbl[(size_t)(m0 + trB) * NDBL + DTRANK + DSTATE + tcB]);
        float* dst = &s_BC[trB * 32 + tcB * 2];
        *reinterpret_cast<float4*>(dst)     = make_float4(vB.x, vB.y, vC.x, vC.y);
        *reinterpret_cast<float4*>(dst + 4) = make_float4(vB.z, vB.w, vC.z, vC.w);
    }
    __syncthreads();

    const int lane  = tid & 31;
    const int warp  = tid >> 5;
    const int npair = lane & 7;
    const int dloc  = warp * 4 + (lane >> 3);
    const int d     = d0 + dloc;
    const int n0    = npair << 1;

    const float Ad0 = -__expf(A_log[d * DSTATE + n0]);
    const float Ad1 = -__expf(A_log[d * DSTATE + n0 + 1]);
    const float Dd  = Dp[d];

    const float2 hs = *reinterpret_cast<const float2*>(
        &HS[(size_t)c * NBDN + ((size_t)b * DINNER + d) * DSTATE + n0]);
    float h0 = hs.x, h1 = hs.y;

#pragma unroll 2
    for (int l = 0; l < LCHUNK; ++l) {
        const float2 dd = *reinterpret_cast<const float2*>(&s_dd[(l * SCAN_D + dloc) * 2]);
        const float4 BC = *reinterpret_cast<const float4*>(&s_BC[l * 32 + n0 * 2]);
        const float e0 = __expf(dd.x * Ad0);
        const float e1 = __expf(dd.x * Ad1);
        h0 = fmaf(e0, h0, dd.y * BC.x);
        h1 = fmaf(e1, h1, dd.y * BC.y);

        float p = fmaf(h0, BC.z, h1 * BC.w);
        p += __shfl_xor_sync(0xffffffffu, p, 1);
        p += __shfl_xor_sync(0xffffffffu, p, 2);
        p += __shfl_xor_sync(0xffffffffu, p, 4);

        if (npair == 0)
            s_y[l * SCAN_D + dloc] = fmaf(Dd, s_xc[l * SCAN_D + dloc], p);
    }
    __syncthreads();

    // store: gate with precomputed silu(z), round to tf32
    {
#pragma unroll
        for (int rr = 0; rr < 2; ++rr) {
            const int r = trow + rr * 32;
            const size_t gm = (size_t)(m0 + r);
            float4 v = *reinterpret_cast<const float4*>(&s_y[r * SCAN_D + tc4]);
            v.x = rtf(v.x * zs[rr].x);
            v.y = rtf(v.y * zs[rr].y);
            v.z = rtf(v.z * zs[rr].z);
            v.w = rtf(v.w * zs[rr].w);
            *reinterpret_cast<float4*>(&y[gm * DINNER + d0 + tc4]) = v;
        }
    }
}

// ----------------------------------------------------------------------------
// Launch
// ----------------------------------------------------------------------------
extern "C" void kernel_launch(void* const* d_in, const int* in_sizes, int n_in,
                              void* d_out, int out_size)
{
    const float* x          = (const float*)d_in[0];
    const float* in_proj_w  = (const float*)d_in[1];
    const float* conv_w     = (const float*)d_in[2];
    const float* conv_b     = (const float*)d_in[3];
    const float* x_proj_w   = (const float*)d_in[4];
    const float* dt_proj_w  = (const float*)d_in[5];
    const float* dt_proj_b  = (const float*)d_in[6];
    const float* A_log      = (const float*)d_in[7];
    const float* D_param    = (const float*)d_in[8];
    const float* out_proj_w = (const float*)d_in[9];
    float* out = (float*)d_out;

    float *xz, *xc, *dbl, *dblp, *dtb, *yb, *xr, *wa, *wb, *P, *Q, *HS;
    cudaGetSymbolAddress((void**)&xz,   g_xz);
    cudaGetSymbolAddress((void**)&xc,   g_xc);
    cudaGetSymbolAddress((void**)&dbl,  g_dbl);
    cudaGetSymbolAddress((void**)&dblp, g_dblp);
    cudaGetSymbolAddress((void**)&dtb,  g_dt);
    cudaGetSymbolAddress((void**)&yb,   g_y);
    cudaGetSymbolAddress((void**)&xr,   g_xr);
    cudaGetSymbolAddress((void**)&wa,   g_wa);
    cudaGetSymbolAddress((void**)&wb,   g_wb);
    cudaGetSymbolAddress((void**)&P,    g_P);
    cudaGetSymbolAddress((void**)&Q,    g_Q);
    cudaGetSymbolAddress((void**)&HS,   g_HS);

    cudaFuncSetAttribute((const void*)mma_gemm<0,false,false,false,false>,
                         cudaFuncAttributeMaxDynamicSharedMemorySize, MMA_SMEM_B);
    cudaFuncSetAttribute((const void*)mma_gemm<0,true,true,true,true>,
                         cudaFuncAttributeMaxDynamicSharedMemorySize, MMA_SMEM_B);
    cudaFuncSetAttribute((const void*)mma_gemm<1,false,true,true,false>,
                         cudaFuncAttributeMaxDynamicSharedMemorySize, MMA_SMEM_B);

    // 0) pre-round big GEMM operands to tf32 (single launch)
    {
        const int n0 = MROWS * DMODEL / 4;
        const int n1 = NXZ * DMODEL / 4;
        const int n2 = DMODEL * DINNER / 4;
        const int tot = n0 + n1 + n2;
        round3_tf32_kernel<<<(tot + 255)/256, 256>>>(
            (const float4*)x,          (float4*)xr, n0,
            (const float4*)in_proj_w,  (float4*)wa, n1,
            (const float4*)out_proj_w, (float4*)wb, n2);
    }

    // 1) xz = x @ in_proj_w^T : M=8192 N=4096 K=1024
    {
        dim3 grid(NXZ/128, MROWS/128);
        mma_gemm<0,false,false,false,false><<<grid, 256, MMA_SMEM_B>>>(
            xr, wa, xz, nullptr, MROWS, NXZ, DMODEL, DMODEL, DMODEL, NXZ);
    }
    // 2) depthwise conv + silu
    {
        int total = MROWS * DINNER / 4;
        conv_silu_kernel<<<total/256, 256>>>(xz, conv_w, conv_b, xc);
    }
    // 3) dbl = xc @ x_proj_w^T : split-K=4 + reduce
    {
        dim3 grid(1, MROWS/128, XPJ_SPLITK);
        mma_gemm<0,true,true,true,true><<<grid, 256, MMA_SMEM_B>>>(
            xc, x_proj_w, dblp, nullptr, MROWS, NDBL, DINNER/XPJ_SPLITK,
            DINNER, DINNER, NDBL);
        int n4 = MROWS * NDBL / 4;
        reduce_splitk_kernel<<<(n4 + 255)/256, 256>>>(
            (const float4*)dblp, (float4*)dbl, n4, n4);
    }
    // 4) dt = softplus(dbl[:, :64] @ dt_proj_w^T + b)
    {
        dim3 grid(DINNER/128, MROWS/128);
        mma_gemm<1,false,true,true,false><<<grid, 256, MMA_SMEM_B>>>(
            dbl, dt_proj_w, dtb, dt_proj_b, MROWS, DINNER, DTRANK,
            NDBL, DTRANK, DINNER);
    }
    // 5) chunked selective scan + gating (v3: packed smem)
    {
        dim3 gridA(DINNER/SCAN_D, BATCH, NCHUNK);
        scan_chunk_kernel<<<gridA, 256>>>(dtb, dbl, xc, A_log, P, Q);
        scan_fix_kernel<<<NBDN/256, 256>>>(P, Q, HS);
        scan_y_kernel<<<gridA, 256>>>(dtb, dbl, xc, xz, A_log, D_param, HS, yb);
    }
    // 6) out = y @ out_proj_w^T : M=8192 N=1024 K=2048
    {
        dim3 grid(DMODEL/128, MROWS/128);
        mma_gemm<0,false,false,false,false><<<grid, 256, MMA_SMEM_B>>>(
            yb, wb, out, nullptr, MROWS, DMODEL, DINNER,
            DINNER, DINNER, DMODEL);
    }
}

// round 11
// speedup vs baseline: 2.0888x; 1.0314x over previous
#include <cuda_runtime.h>
#include <math.h>
#include <stdint.h>

// Problem constants
#define BATCH   4
#define SEQ     2048
#define DMODEL  1024
#define DINNER  2048
#define DSTATE  16
#define DTRANK  64
#define DCONV   4
#define MROWS   (BATCH*SEQ)          // 8192
#define NXZ     (2*DINNER)           // 4096
#define NDBL    (DTRANK + 2*DSTATE)  // 96
#define NCHUNK  32
#define LCHUNK  (SEQ/NCHUNK)         // 64
#define XPJ_SPLITK 4
#define NBDN    (BATCH*DINNER*DSTATE)    // 131072

// ----------------------------------------------------------------------------
// Scratch (device globals; no runtime allocation allowed)
// ----------------------------------------------------------------------------
__device__ float g_xz [(size_t)MROWS * NXZ];
__device__ float g_xc [(size_t)MROWS * DINNER];
__device__ float g_dbl[(size_t)MROWS * NDBL];
__device__ float g_dblp[(size_t)XPJ_SPLITK * MROWS * NDBL];
__device__ float g_dt [(size_t)MROWS * DINNER];
__device__ float g_y  [(size_t)MROWS * DINNER];   // tf32-rounded
__device__ float g_xr [(size_t)MROWS * DMODEL];   // tf32-rounded x
__device__ float g_wa [(size_t)NXZ   * DMODEL];   // tf32-rounded in_proj_w
__device__ float g_wb [(size_t)DMODEL* DINNER];   // tf32-rounded out_proj_w
// chunked-scan state, layout [chunk][b*d*n]
#define SCAN_ST ((size_t)NCHUNK * NBDN)
__device__ float g_P [SCAN_ST];
__device__ float g_Q [SCAN_ST];
__device__ float g_HS[SCAN_ST];

// ============================================================================
// mma.sync tf32 helpers
// ============================================================================
__device__ __forceinline__ uint32_t f2tf32(float x) {
    uint32_t r;
    asm("cvt.rna.tf32.f32 %0, %1;" : "=r"(r) : "f"(x));
    return r;
}
__device__ __forceinline__ float rtf(float x) {
    return __uint_as_float(f2tf32(x));
}
__device__ __forceinline__ uint32_t tf32_bits(uint32_t v) {
    return f2tf32(__uint_as_float(v));
}
__device__ __forceinline__ void mma_tf32(float* c, const uint32_t* a, const uint32_t* b) {
    asm volatile(
        "mma.sync.aligned.m16n8k8.row.col.f32.tf32.tf32.f32 "
        "{%0,%1,%2,%3}, {%4,%5,%6,%7}, {%8,%9}, {%0,%1,%2,%3};"
        : "+f"(c[0]), "+f"(c[1]), "+f"(c[2]), "+f"(c[3])
        : "r"(a[0]), "r"(a[1]), "r"(a[2]), "r"(a[3]), "r"(b[0]), "r"(b[1]));
}
__device__ __forceinline__ void ldsm_x4(uint32_t* r, uint32_t addr) {
    asm volatile(
        "ldmatrix.sync.aligned.m8n8.x4.shared.b16 {%0,%1,%2,%3}, [%4];"
        : "=r"(r[0]), "=r"(r[1]), "=r"(r[2]), "=r"(r[3]) : "r"(addr));
}
__device__ __forceinline__ uint32_t smem_u32(const void* p) {
    uint32_t a;
    asm("{ .reg .u64 t; cvta.to.shared.u64 t, %1; cvt.u32.u64 %0, t; }"
        : "=r"(a) : "l"(p));
    return a;
}
__device__ __forceinline__ void cp_async16(uint32_t dst, const void* src) {
    asm volatile("cp.async.cg.shared.global [%0], [%1], 16;"
                 :: "r"(dst), "l"(src) : "memory");
}
__device__ __forceinline__ void cp_async16z(uint32_t dst, const void* src, bool valid) {
    uint32_t sz = valid ? 16u : 0u;
    asm volatile("cp.async.cg.shared.global [%0], [%1], 16, %2;"
                 :: "r"(dst), "l"(src), "r"(sz) : "memory");
}
#define CP_COMMIT() asm volatile("cp.async.commit_group;" ::: "memory")
#define CP_WAIT(n)  asm volatile("cp.async.wait_group %0;" :: "n"(n) : "memory")

// ============================================================================
// tf32 MMA NT GEMM: C[M,N] = A[M,K]*B[N,K]^T.
// CTA 128x128x32, 256 thr, warp tile 64x32, 2-stage cp.async, stride 36.
// Fragment loads via ldmatrix.x4 (4x fewer LDS issues); identical math.
// ============================================================================
#define MMA_STRIDE   36
#define MMA_STAGE_F  (128 * MMA_STRIDE)
#define MMA_STAGE_B  (MMA_STAGE_F * 4)
#define MMA_SMEM_B   (4 * MMA_STAGE_B)           // 73728 bytes

template<int EPI, bool NGUARD, bool CVTA, bool CVTB, bool SPLITK>
__global__ void __launch_bounds__(256, 2)
mma_gemm(const float* __restrict__ A, const float* __restrict__ B,
         float* __restrict__ C, const float* __restrict__ bias,
         int M, int N, int K, int lda, int ldb, int ldc)
{
    extern __shared__ float sm[];
    const uint32_t smB = smem_u32(sm);

    if (SPLITK) {
        const int z = blockIdx.z;
        A += (size_t)z * K;
        B += (size_t)z * K;
        C += (size_t)z * M * (size_t)ldc;
    }

    const int tid    = threadIdx.x;
    const int lane   = tid & 31;
    const int wid    = tid >> 5;
    const int warp_m = wid >> 2;
    const int warp_n = wid & 3;
    const int lr     = lane >> 2;
    const int lc     = lane & 3;

    const int rowBase = blockIdx.y * 128;
    const int colBase = blockIdx.x * 128;

    // per-lane ldmatrix row offsets (bytes within a stage)
    // A x4 tile set for warp tile mt: rows (warp_m*64+mt*16 + lane&15), k-half (lane>>4)
    const uint32_t aOff =
        (((warp_m * 64 + (lane & 15)) * MMA_STRIDE) + (lane >> 4) * 4) * 4;
    // B x4 tile set for nt pair j: n-rows (warp_n*32 + j*16 + (lane>>4)*8 + lane&7),
    // k-half ((lane>>3)&1)
    const uint32_t bOff =
        (((warp_n * 32 + (lane >> 4) * 8 + (lane & 7)) * MMA_STRIDE) +
         ((lane >> 3) & 1) * 4) * 4;

    float acc[4][4][4];
#pragma unroll
    for (int mt = 0; mt < 4; ++mt)
#pragma unroll
        for (int nt = 0; nt < 4; ++nt)
#pragma unroll
            for (int i = 0; i < 4; ++i) acc[mt][nt][i] = 0.f;

    const int T = K >> 5;

    auto load_stage = [&](int s, int kt) {
        const int kOff = kt << 5;
        const uint32_t aB = smB + s * MMA_STAGE_B;
        const uint32_t bB = smB + 2 * MMA_STAGE_B + s * MMA_STAGE_B;
#pragma unroll
        for (int i = 0; i < 4; ++i) {
            const int chunk = tid + (i << 8);
            const int row = chunk >> 3;
            const int c4  = chunk & 7;
            const uint32_t so = row * (MMA_STRIDE * 4) + c4 * 16;
            cp_async16(aB + so, &A[(size_t)(rowBase + row) * lda + kOff + c4 * 4]);
            if (NGUARD) {
                const bool ok = (colBase + row) < N;
                const int  br = ok ? (colBase + row) : 0;
                cp_async16z(bB + so, &B[(size_t)br * ldb + kOff + c4 * 4], ok);
            } else {
                cp_async16(bB + so, &B[(size_t)(colBase + row) * ldb + kOff + c4 * 4]);
            }
        }
        CP_COMMIT();
    };

    load_stage(0, 0);

    for (int kt = 0; kt < T; ++kt) {
        const int s = kt & 1;
        if (kt + 1 < T) {
            load_stage(s ^ 1, kt + 1);
            CP_WAIT(1);
        } else {
            CP_WAIT(0);
        }
        __syncthreads();

        const uint32_t aS = smB + s * MMA_STAGE_B + aOff;
        const uint32_t bS = smB + 2 * MMA_STAGE_B + s * MMA_STAGE_B + bOff;

#pragma unroll
        for (int kk = 0; kk < 4; ++kk) {
            const uint32_t kB = kk * 32;            // 8 tf32 = 32 bytes
            uint32_t af[4][4];
#pragma unroll
            for (int mt = 0; mt < 4; ++mt) {
                ldsm_x4(af[mt], aS + mt * (16 * MMA_STRIDE * 4) + kB);
                if (CVTA) {
#pragma unroll
                    for (int i = 0; i < 4; ++i) af[mt][i] = tf32_bits(af[mt][i]);
                }
            }
            uint32_t bf[4][2];
#pragma unroll
            for (int j = 0; j < 2; ++j) {
                uint32_t bt[4];
                ldsm_x4(bt, bS + j * (16 * MMA_STRIDE * 4) + kB);
                if (CVTB) {
#pragma unroll
                    for (int i = 0; i < 4; ++i) bt[i] = tf32_bits(bt[i]);
                }
                bf[2*j][0]   = bt[0]; bf[2*j][1]   = bt[1];
                bf[2*j+1][0] = bt[2]; bf[2*j+1][1] = bt[3];
            }
#pragma unroll
            for (int mt = 0; mt < 4; ++mt)
#pragma unroll
                for (int nt = 0; nt < 4; ++nt)
                    mma_tf32(acc[mt][nt], af[mt], bf[nt]);
        }
        __syncthreads();
    }

#pragma unroll
    for (int mt = 0; mt < 4; ++mt) {
        const int row = rowBase + warp_m * 64 + mt * 16 + lr;
#pragma unroll
        for (int nt = 0; nt < 4; ++nt) {
            const int col = colBase + warp_n * 32 + nt * 8 + 2 * lc;
            if (NGUARD && col >= N) continue;
            float v[4] = {acc[mt][nt][0], acc[mt][nt][1],
                          acc[mt][nt][2], acc[mt][nt][3]};
            if (EPI == 1) {
                const float b0 = bias[col], b1 = bias[col + 1];
                v[0] += b0; v[1] += b1; v[2] += b0; v[3] += b1;
#pragma unroll
                for (int i = 0; i < 4; ++i)
                    v[i] = fmaxf(v[i], 0.f) + log1pf(__expf(-fabsf(v[i])));
            }
            *reinterpret_cast<float2*>(&C[(size_t)row * ldc + col]) =
                make_float2(v[0], v[1]);
            *reinterpret_cast<float2*>(&C[(size_t)(row + 8) * ldc + col]) =
                make_float2(v[2], v[3]);
        }
    }
}

// ----------------------------------------------------------------------------
// split-K reduce
// ----------------------------------------------------------------------------
__global__ void reduce_splitk_kernel(const float4* __restrict__ part,
                                     float4* __restrict__ out, int n4, int stride4)
{
    int i = blockIdx.x * blockDim.x + threadIdx.x;
    if (i < n4) {
        float4 a = part[i];
        float4 b = part[i + stride4];
        float4 c = part[i + 2 * stride4];
        float4 d = part[i + 3 * stride4];
        out[i] = make_float4(a.x + b.x + c.x + d.x, a.y + b.y + c.y + d.y,
                             a.z + b.z + c.z + d.z, a.w + b.w + c.w + d.w);
    }
}

// ----------------------------------------------------------------------------
// Round three fp32 arrays to tf32 (rna) in one launch.
// ----------------------------------------------------------------------------
__global__ void round3_tf32_kernel(const float4* __restrict__ inA, float4* __restrict__ outA, int n0,
                                   const float4* __restrict__ inB, float4* __restrict__ outB, int n1,
                                   const float4* __restrict__ inC, float4* __restrict__ outC, int n2)
{
    int i = blockIdx.x * blockDim.x + threadIdx.x;
    const float4* in;
    float4* out;
    int j;
    if (i < n0)            { in = inA; out = outA; j = i; }
    else if (i < n0 + n1)  { in = inB; out = outB; j = i - n0; }
    else if (i < n0+n1+n2) { in = inC; out = outC; j = i - n0 - n1; }
    else return;
    float4 v = in[j];
    v.x = rtf(v.x); v.y = rtf(v.y); v.z = rtf(v.z); v.w = rtf(v.w);
    out[j] = v;
}

// ----------------------------------------------------------------------------
// Depthwise causal conv (width 4) + SiLU — float4 over channels
// ----------------------------------------------------------------------------
__global__ void conv_silu_kernel(const float* __restrict__ xz,
                                 const float* __restrict__ w,
                                 const float* __restrict__ b,
                                 float* __restrict__ xc)
{
    int i = blockIdx.x * blockDim.x + threadIdx.x;
    int d4 = (i & 511) << 2;
    int m  = i >> 9;
    int l  = m & (SEQ - 1);

    float4 wv[4];
#pragma unroll
    for (int c = 0; c < 4; ++c)
        wv[c] = *reinterpret_cast<const float4*>(&w[(d4 + c) * DCONV]);
    float4 acc = *reinterpret_cast<const float4*>(&b[d4]);

#pragma unroll
    for (int j = 0; j < DCONV; ++j) {
        int lj = l - (DCONV - 1) + j;
        if (lj >= 0) {
            float4 xv = *reinterpret_cast<const float4*>(
                &xz[(size_t)(m - (DCONV - 1) + j) * NXZ + d4]);
            acc.x = fmaf(((const float*)&wv[0])[j], xv.x, acc.x);
            acc.y = fmaf(((const float*)&wv[1])[j], xv.y, acc.y);
            acc.z = fmaf(((const float*)&wv[2])[j], xv.z, acc.z);
            acc.w = fmaf(((const float*)&wv[3])[j], xv.w, acc.w);
        }
    }
    acc.x = acc.x / (1.f + __expf(-acc.x));
    acc.y = acc.y / (1.f + __expf(-acc.y));
    acc.z = acc.z / (1.f + __expf(-acc.z));
    acc.w = acc.w / (1.f + __expf(-acc.w));
    *reinterpret_cast<float4*>(&xc[(size_t)m * DINNER + d4]) = acc;
}

// ============================================================================
// Chunked selective scan v3 (round-9 proven form).
// ============================================================================
#define SCAN_D 32

__global__ void __launch_bounds__(256) scan_chunk_kernel(
    const float* __restrict__ dt,  const float* __restrict__ dbl,
    const float* __restrict__ xc,  const float* __restrict__ A_log,
    float* __restrict__ P, float* __restrict__ Q)
{
    __shared__ float s_dd[LCHUNK * SCAN_D * 2];   // {dt, dtx} pairs
    __shared__ float s_B [LCHUNK * 16];

    const int tid  = threadIdx.x;
    const int d0   = blockIdx.x * SCAN_D;
    const int b    = blockIdx.y;
    const int c    = blockIdx.z;
    const int m0   = b * SEQ + c * LCHUNK;

    {
        const int trow = tid >> 3;
        const int tc4  = (tid & 7) << 2;
#pragma unroll
        for (int r = trow; r < LCHUNK; r += 32) {
            const size_t gm = (size_t)(m0 + r);
            float4 vdt = *reinterpret_cast<const float4*>(&dt[gm * DINNER + d0 + tc4]);
            float4 vxc = *reinterpret_cast<const float4*>(&xc[gm * DINNER + d0 + tc4]);
            float* dst = &s_dd[(r * SCAN_D + tc4) * 2];
            *reinterpret_cast<float4*>(dst) =
                make_float4(vdt.x, vdt.x * vxc.x, vdt.y, vdt.y * vxc.y);
            *reinterpret_cast<float4*>(dst + 4) =
                make_float4(vdt.z, vdt.z * vxc.z, vdt.w, vdt.w * vxc.w);
        }
        const int trB = tid >> 2;
        const int tcB = (tid & 3) << 2;
        *reinterpret_cast<float4*>(&s_B[trB * 16 + tcB]) =
            *reinterpret_cast<const float4*>(&dbl[(size_t)(m0 + trB) * NDBL + DTRANK + tcB]);
    }
    __syncthreads();

    const int lane  = tid & 31;
    const int warp  = tid >> 5;
    const int npair = lane & 7;
    const int dloc  = warp * 4 + (lane >> 3);
    const int d     = d0 + dloc;
    const int n0    = npair << 1;

    const float Ad0 = -__expf(A_log[d * DSTATE + n0]);
    const float Ad1 = -__expf(A_log[d * DSTATE + n0 + 1]);
    float P0 = 1.f, P1 = 1.f, h0 = 0.f, h1 = 0.f;

#pragma unroll 4
    for (int l = 0; l < LCHUNK; ++l) {
        const float2 dd = *reinterpret_cast<const float2*>(&s_dd[(l * SCAN_D + dloc) * 2]);
        const float2 B2 = *reinterpret_cast<const float2*>(&s_B[l * 16 + n0]);
        const float e0 = __expf(dd.x * Ad0);
        const float e1 = __expf(dd.x * Ad1);
        P0 *= e0; P1 *= e1;
        h0 = fmaf(e0, h0, dd.y * B2.x);
        h1 = fmaf(e1, h1, dd.y * B2.y);
    }
    const size_t idx = (size_t)c * NBDN + ((size_t)b * DINNER + d) * DSTATE + n0;
    *reinterpret_cast<float2*>(&P[idx]) = make_float2(P0, P1);
    *reinterpret_cast<float2*>(&Q[idx]) = make_float2(h0, h1);
}

__global__ void __launch_bounds__(256) scan_fix_kernel(
    const float* __restrict__ P, const float* __restrict__ Q,
    float* __restrict__ HS)
{
    const size_t i = (size_t)blockIdx.x * blockDim.x + threadIdx.x;
    float h = 0.f;
#pragma unroll
    for (int c = 0; c < NCHUNK; ++c) {
        const size_t k = (size_t)c * NBDN + i;
        HS[k] = h;
        h = fmaf(P[k], h, Q[k]);
    }
}

__global__ void __launch_bounds__(256) scan_y_kernel(
    const float* __restrict__ dt,  const float* __restrict__ dbl,
    const float* __restrict__ xc,  const float* __restrict__ xz,
    const float* __restrict__ A_log, const float* __restrict__ Dp,
    const float* __restrict__ HS, float* __restrict__ y)
{
    __shared__ float s_dd[LCHUNK * SCAN_D * 2];   // {dt, dtx}
    __shared__ float s_xc[LCHUNK * SCAN_D];
    __shared__ float s_BC[LCHUNK * 32];           // {B0,B1,C0,C1} per npair
    __shared__ float s_y [LCHUNK * SCAN_D];

    const int tid  = threadIdx.x;
    const int d0   = blockIdx.x * SCAN_D;
    const int b    = blockIdx.y;
    const int c    = blockIdx.z;
    const int m0   = b * SEQ + c * LCHUNK;

    const int trow = tid >> 3;
    const int tc4  = (tid & 7) << 2;
    float4 zs[2];

    {
#pragma unroll
        for (int rr = 0; rr < 2; ++rr) {
            const int r = trow + rr * 32;
            const size_t gm = (size_t)(m0 + r);
            float4 vdt = *reinterpret_cast<const float4*>(&dt[gm * DINNER + d0 + tc4]);
            float4 vxc = *reinterpret_cast<const float4*>(&xc[gm * DINNER + d0 + tc4]);
            float4 vz  = *reinterpret_cast<const float4*>(&xz[gm * NXZ + DINNER + d0 + tc4]);
            *reinterpret_cast<float4*>(&s_xc[r * SCAN_D + tc4]) = vxc;
            float* dst = &s_dd[(r * SCAN_D + tc4) * 2];
            *reinterpret_cast<float4*>(dst) =
                make_float4(vdt.x, vdt.x * vxc.x, vdt.y, vdt.y * vxc.y);
            *reinterpret_cast<float4*>(dst + 4) =
                make_float4(vdt.z, vdt.z * vxc.z, vdt.w, vdt.w * vxc.w);
            vz.x = vz.x / (1.f + __expf(-vz.x));
            vz.y = vz.y / (1.f + __expf(-vz.y));
            vz.z = vz.z / (1.f + __expf(-vz.z));
            vz.w = vz.w / (1.f + __expf(-vz.w));
            zs[rr] = vz;
        }
        const int trB = tid >> 2;
        const int tcB = (tid & 3) << 2;
        float4 vB = *reinterpret_cast<const float4*>(&dbl[(size_t)(m0 + trB) * NDBL + DTRANK + tcB]);
        float4 vC = *reinterpret_cast<const float4*>(&dbl[(size_t)(m0 + trB) * NDBL + DTRANK + DSTATE + tcB]);
        float* dst = &s_BC[trB * 32 + tcB * 2];
        *reinterpret_cast<float4*>(dst)     = make_float4(vB.x, vB.y, vC.x, vC.y);
        *reinterpret_cast<float4*>(dst + 4) = make_float4(vB.z, vB.w, vC.z, vC.w);
    }
    __syncthreads();

    const int lane  = tid & 31;
    const int warp  = tid >> 5;
    const int npair = lane & 7;
    const int dloc  = warp * 4 + (lane >> 3);
    const int d     = d0 + dloc;
    const int n0    = npair << 1;

    const float Ad0 = -__expf(A_log[d * DSTATE + n0]);
    const float Ad1 = -__expf(A_log[d * DSTATE + n0 + 1]);
    const float Dd  = Dp[d];

    const float2 hs = *reinterpret_cast<const float2*>(
        &HS[(size_t)c * NBDN + ((size_t)b * DINNER + d) * DSTATE + n0]);
    float h0 = hs.x, h1 = hs.y;

#pragma unroll 2
    for (int l = 0; l < LCHUNK; ++l) {
        const float2 dd = *reinterpret_cast<const float2*>(&s_dd[(l * SCAN_D + dloc) * 2]);
        const float4 BC = *reinterpret_cast<const float4*>(&s_BC[l * 32 + n0 * 2]);
        const float e0 = __expf(dd.x * Ad0);
        const float e1 = __expf(dd.x * Ad1);
        h0 = fmaf(e0, h0, dd.y * BC.x);
        h1 = fmaf(e1, h1, dd.y * BC.y);

        float p = fmaf(h0, BC.z, h1 * BC.w);
        p += __shfl_xor_sync(0xffffffffu, p, 1);
        p += __shfl_xor_sync(0xffffffffu, p, 2);
        p += __shfl_xor_sync(0xffffffffu, p, 4);

        if (npair == 0)
            s_y[l * SCAN_D + dloc] = fmaf(Dd, s_xc[l * SCAN_D + dloc], p);
    }
    __syncthreads();

    {
#pragma unroll
        for (int rr = 0; rr < 2; ++rr) {
            const int r = trow + rr * 32;
            const size_t gm = (size_t)(m0 + r);
            float4 v = *reinterpret_cast<const float4*>(&s_y[r * SCAN_D + tc4]);
            v.x = rtf(v.x * zs[rr].x);
            v.y = rtf(v.y * zs[rr].y);
            v.z = rtf(v.z * zs[rr].z);
            v.w = rtf(v.w * zs[rr].w);
            *reinterpret_cast<float4*>(&y[gm * DINNER + d0 + tc4]) = v;
        }
    }
}

// ----------------------------------------------------------------------------
// Launch
// ----------------------------------------------------------------------------
extern "C" void kernel_launch(void* const* d_in, const int* in_sizes, int n_in,
                              void* d_out, int out_size)
{
    const float* x          = (const float*)d_in[0];
    const float* in_proj_w  = (const float*)d_in[1];
    const float* conv_w     = (const float*)d_in[2];
    const float* conv_b     = (const float*)d_in[3];
    const float* x_proj_w   = (const float*)d_in[4];
    const float* dt_proj_w  = (const float*)d_in[5];
    const float* dt_proj_b  = (const float*)d_in[6];
    const float* A_log      = (const float*)d_in[7];
    const float* D_param    = (const float*)d_in[8];
    const float* out_proj_w = (const float*)d_in[9];
    float* out = (float*)d_out;

    float *xz, *xc, *dbl, *dblp, *dtb, *yb, *xr, *wa, *wb, *P, *Q, *HS;
    cudaGetSymbolAddress((void**)&xz,   g_xz);
    cudaGetSymbolAddress((void**)&xc,   g_xc);
    cudaGetSymbolAddress((void**)&dbl,  g_dbl);
    cudaGetSymbolAddress((void**)&dblp, g_dblp);
    cudaGetSymbolAddress((void**)&dtb,  g_dt);
    cudaGetSymbolAddress((void**)&yb,   g_y);
    cudaGetSymbolAddress((void**)&xr,   g_xr);
    cudaGetSymbolAddress((void**)&wa,   g_wa);
    cudaGetSymbolAddress((void**)&wb,   g_wb);
    cudaGetSymbolAddress((void**)&P,    g_P);
    cudaGetSymbolAddress((void**)&Q,    g_Q);
    cudaGetSymbolAddress((void**)&HS,   g_HS);

    cudaFuncSetAttribute((const void*)mma_gemm<0,false,false,false,false>,
                         cudaFuncAttributeMaxDynamicSharedMemorySize, MMA_SMEM_B);
    cudaFuncSetAttribute((const void*)mma_gemm<0,true,true,true,true>,
                         cudaFuncAttributeMaxDynamicSharedMemorySize, MMA_SMEM_B);
    cudaFuncSetAttribute((const void*)mma_gemm<1,false,true,true,false>,
                         cudaFuncAttributeMaxDynamicSharedMemorySize, MMA_SMEM_B);

    // 0) pre-round big GEMM operands to tf32 (single launch)
    {
        const int n0 = MROWS * DMODEL / 4;
        const int n1 = NXZ * DMODEL / 4;
        const int n2 = DMODEL * DINNER / 4;
        const int tot = n0 + n1 + n2;
        round3_tf32_kernel<<<(tot + 255)/256, 256>>>(
            (const float4*)x,          (float4*)xr, n0,
            (const float4*)in_proj_w,  (float4*)wa, n1,
            (const float4*)out_proj_w, (float4*)wb, n2);
    }

    // 1) xz = x @ in_proj_w^T : M=8192 N=4096 K=1024
    {
        dim3 grid(NXZ/128, MROWS/128);
        mma_gemm<0,false,false,false,false><<<grid, 256, MMA_SMEM_B>>>(
            xr, wa, xz, nullptr, MROWS, NXZ, DMODEL, DMODEL, DMODEL, NXZ);
    }
    // 2) depthwise conv + silu
    {
        int total = MROWS * DINNER / 4;
        conv_silu_kernel<<<total/256, 256>>>(xz, conv_w, conv_b, xc);
    }
    // 3) dbl = xc @ x_proj_w^T : split-K=4 + reduce
    {
        dim3 grid(1, MROWS/128, XPJ_SPLITK);
        mma_gemm<0,true,true,true,true><<<grid, 256, MMA_SMEM_B>>>(
            xc, x_proj_w, dblp, nullptr, MROWS, NDBL, DINNER/XPJ_SPLITK,
            DINNER, DINNER, NDBL);
        int n4 = MROWS * NDBL / 4;
        reduce_splitk_kernel<<<(n4 + 255)/256, 256>>>(
            (const float4*)dblp, (float4*)dbl, n4, n4);
    }
    // 4) dt = softplus(dbl[:, :64] @ dt_proj_w^T + b)
    {
        dim3 grid(DINNER/128, MROWS/128);
        mma_gemm<1,false,true,true,false><<<grid, 256, MMA_SMEM_B>>>(
            dbl, dt_proj_w, dtb, dt_proj_b, MROWS, DINNER, DTRANK,
            NDBL, DTRANK, DINNER);
    }
    // 5) chunked selective scan + gating
    {
        dim3 gridA(DINNER/SCAN_D, BATCH, NCHUNK);
        scan_chunk_kernel<<<gridA, 256>>>(dtb, dbl, xc, A_log, P, Q);
        scan_fix_kernel<<<NBDN/256, 256>>>(P, Q, HS);
        scan_y_kernel<<<gridA, 256>>>(dtb, dbl, xc, xz, A_log, D_param, HS, yb);
    }
    // 6) out = y @ out_proj_w^T : M=8192 N=1024 K=2048
    {
        dim3 grid(DMODEL/128, MROWS/128);
        mma_gemm<0,false,false,false,false><<<grid, 256, MMA_SMEM_B>>>(
            yb, wb, out, nullptr, MROWS, DMODEL, DINNER,
            DINNER, DINNER, DMODEL);
    }
}